// round 6
// baseline (speedup 1.0000x reference)
#include <cuda_runtime.h>

// ---------------- scratch (static device globals; no allocs) ----------------
__device__ float d_scale_n[128];
__device__ float d_scale_c[256];
__device__ float d_nodes[4096 * 128];   // relu(node_feats @ w_n^T + b_node)
__device__ float d_AB[4096 * 256];      // [ nodes@W1^T | nodes@W2^T ]
__device__ float d_gamma[16 * 128];
__device__ float d_beta[16 * 128];

__device__ __forceinline__ float warp_sum(float v) {
#pragma unroll
    for (int o = 16; o; o >>= 1) v += __shfl_xor_sync(0xffffffffu, v, o);
    return v;
}

// ---------------- K1: weight-norm scales ----------------
// 384 warps: rows 0..127 -> v_node, 128..383 -> v_cond
__global__ void k_scales(const float* __restrict__ v_node, const float* __restrict__ g_node,
                         const float* __restrict__ v_cond, const float* __restrict__ g_cond) {
    int w = (blockIdx.x * blockDim.x + threadIdx.x) >> 5;
    int lane = threadIdx.x & 31;
    const float* src;
    float g;
    float* dst;
    if (w < 128) { src = v_node + w * 512; g = g_node[w]; dst = d_scale_n + w; }
    else         { int r = w - 128; src = v_cond + r * 512; g = g_cond[r]; dst = d_scale_c + r; }
    float s = 0.f;
#pragma unroll
    for (int k = lane; k < 512; k += 32) { float v = src[k]; s += v * v; }
    s = warp_sum(s);
    if (lane == 0) *dst = g * rsqrtf(s);
}

// ---------------- K_cond: gb = cond @ w_c^T + b_cond -> gamma/beta ----------------
// 4096 warps, one per (b, c)
__global__ void k_cond(const float* __restrict__ cond, const float* __restrict__ vc,
                       const float* __restrict__ bc) {
    int w = (blockIdx.x * blockDim.x + threadIdx.x) >> 5;
    int lane = threadIdx.x & 31;
    int b = w >> 8, c = w & 255;
    const float* cr = cond + b * 512;
    const float* vr = vc + c * 512;
    float s = 0.f;
#pragma unroll
    for (int k = lane; k < 512; k += 32) s += cr[k] * vr[k];
    s = warp_sum(s);
    if (lane == 0) {
        float r = s * d_scale_c[c] + bc[c];
        if (c < 128) d_gamma[b * 128 + c] = r + 1.f;
        else         d_beta[b * 128 + (c - 128)] = r;
    }
}

// ---------------- K2: nodes = relu(node_feats @ (v_node*scale)^T + b_node) ----------------
// 4096x128, K=512. Block: 128 threads, tile BM=32 x BN=128, thread micro-tile 8x4.
__global__ void __launch_bounds__(128) k_nodes(const float* __restrict__ nf,
                                               const float* __restrict__ vn,
                                               const float* __restrict__ bn) {
    __shared__ float As[16][32];
    __shared__ float Bs[16][128];
    int tid = threadIdx.x;
    int mb = blockIdx.x * 32;
    int tx = tid & 31, ty = tid >> 5;
    int m0 = ty * 8, n0 = tx * 4;

    float acc[8][4];
#pragma unroll
    for (int i = 0; i < 8; i++)
#pragma unroll
        for (int j = 0; j < 4; j++) acc[i][j] = 0.f;

    int lr = tid & 31;          // A row in tile
    int lk = (tid >> 5) * 4;    // A k-group
    int bn_ = tid >> 2;         // B base row (+0,+32,+64,+96)
    int bk = (tid & 3) * 4;     // B k-group

    for (int k0 = 0; k0 < 512; k0 += 16) {
        float4 a4 = *(const float4*)(nf + (size_t)(mb + lr) * 512 + k0 + lk);
        float4 b0 = *(const float4*)(vn + (size_t)(bn_ +  0) * 512 + k0 + bk);
        float4 b1 = *(const float4*)(vn + (size_t)(bn_ + 32) * 512 + k0 + bk);
        float4 b2 = *(const float4*)(vn + (size_t)(bn_ + 64) * 512 + k0 + bk);
        float4 b3 = *(const float4*)(vn + (size_t)(bn_ + 96) * 512 + k0 + bk);
        __syncthreads();
        As[lk + 0][lr] = a4.x; As[lk + 1][lr] = a4.y; As[lk + 2][lr] = a4.z; As[lk + 3][lr] = a4.w;
        Bs[bk + 0][bn_ +  0] = b0.x; Bs[bk + 1][bn_ +  0] = b0.y; Bs[bk + 2][bn_ +  0] = b0.z; Bs[bk + 3][bn_ +  0] = b0.w;
        Bs[bk + 0][bn_ + 32] = b1.x; Bs[bk + 1][bn_ + 32] = b1.y; Bs[bk + 2][bn_ + 32] = b1.z; Bs[bk + 3][bn_ + 32] = b1.w;
        Bs[bk + 0][bn_ + 64] = b2.x; Bs[bk + 1][bn_ + 64] = b2.y; Bs[bk + 2][bn_ + 64] = b2.z; Bs[bk + 3][bn_ + 64] = b2.w;
        Bs[bk + 0][bn_ + 96] = b3.x; Bs[bk + 1][bn_ + 96] = b3.y; Bs[bk + 2][bn_ + 96] = b3.z; Bs[bk + 3][bn_ + 96] = b3.w;
        __syncthreads();
#pragma unroll
        for (int k = 0; k < 16; k++) {
            float a[8];
            *(float4*)&a[0] = *(const float4*)&As[k][m0];
            *(float4*)&a[4] = *(const float4*)&As[k][m0 + 4];
            float4 b = *(const float4*)&Bs[k][n0];
#pragma unroll
            for (int i = 0; i < 8; i++) {
                acc[i][0] = fmaf(a[i], b.x, acc[i][0]);
                acc[i][1] = fmaf(a[i], b.y, acc[i][1]);
                acc[i][2] = fmaf(a[i], b.z, acc[i][2]);
                acc[i][3] = fmaf(a[i], b.w, acc[i][3]);
            }
        }
    }

    float sc[4], bb[4];
#pragma unroll
    for (int j = 0; j < 4; j++) { sc[j] = d_scale_n[n0 + j]; bb[j] = bn[n0 + j]; }
#pragma unroll
    for (int i = 0; i < 8; i++) {
        float4 o;
        o.x = fmaxf(fmaf(acc[i][0], sc[0], bb[0]), 0.f);
        o.y = fmaxf(fmaf(acc[i][1], sc[1], bb[1]), 0.f);
        o.z = fmaxf(fmaf(acc[i][2], sc[2], bb[2]), 0.f);
        o.w = fmaxf(fmaf(acc[i][3], sc[3], bb[3]), 0.f);
        *(float4*)&d_nodes[(size_t)(mb + m0 + i) * 128 + n0] = o;
    }
}

// ---------------- K3: AB = nodes @ [W1|W2]^T  (4096 x 256, K=128) ----------------
// blockIdx.y selects W half: y=0 -> w_film[c][0..127], y=1 -> w_film[c][128..255]
__global__ void __launch_bounds__(128) k_ab(const float* __restrict__ wf) {
    __shared__ float As[16][32];
    __shared__ float Bs[16][128];
    int tid = threadIdx.x;
    int mb = blockIdx.x * 32;
    int nb = blockIdx.y * 128;
    int tx = tid & 31, ty = tid >> 5;
    int m0 = ty * 8, n0 = tx * 4;

    float acc[8][4];
#pragma unroll
    for (int i = 0; i < 8; i++)
#pragma unroll
        for (int j = 0; j < 4; j++) acc[i][j] = 0.f;

    int lr = tid & 31;
    int lk = (tid >> 5) * 4;
    int bn_ = tid >> 2;
    int bk = (tid & 3) * 4;
    const float* wbase = wf + nb;  // +0 for W1 columns, +128 for W2 columns

    for (int k0 = 0; k0 < 128; k0 += 16) {
        float4 a4 = *(const float4*)(d_nodes + (size_t)(mb + lr) * 128 + k0 + lk);
        float4 b0 = *(const float4*)(wbase + (size_t)(bn_ +  0) * 256 + k0 + bk);
        float4 b1 = *(const float4*)(wbase + (size_t)(bn_ + 32) * 256 + k0 + bk);
        float4 b2 = *(const float4*)(wbase + (size_t)(bn_ + 64) * 256 + k0 + bk);
        float4 b3 = *(const float4*)(wbase + (size_t)(bn_ + 96) * 256 + k0 + bk);
        __syncthreads();
        As[lk + 0][lr] = a4.x; As[lk + 1][lr] = a4.y; As[lk + 2][lr] = a4.z; As[lk + 3][lr] = a4.w;
        Bs[bk + 0][bn_ +  0] = b0.x; Bs[bk + 1][bn_ +  0] = b0.y; Bs[bk + 2][bn_ +  0] = b0.z; Bs[bk + 3][bn_ +  0] = b0.w;
        Bs[bk + 0][bn_ + 32] = b1.x; Bs[bk + 1][bn_ + 32] = b1.y; Bs[bk + 2][bn_ + 32] = b1.z; Bs[bk + 3][bn_ + 32] = b1.w;
        Bs[bk + 0][bn_ + 64] = b2.x; Bs[bk + 1][bn_ + 64] = b2.y; Bs[bk + 2][bn_ + 64] = b2.z; Bs[bk + 3][bn_ + 64] = b2.w;
        Bs[bk + 0][bn_ + 96] = b3.x; Bs[bk + 1][bn_ + 96] = b3.y; Bs[bk + 2][bn_ + 96] = b3.z; Bs[bk + 3][bn_ + 96] = b3.w;
        __syncthreads();
#pragma unroll
        for (int k = 0; k < 16; k++) {
            float a[8];
            *(float4*)&a[0] = *(const float4*)&As[k][m0];
            *(float4*)&a[4] = *(const float4*)&As[k][m0 + 4];
            float4 b = *(const float4*)&Bs[k][n0];
#pragma unroll
            for (int i = 0; i < 8; i++) {
                acc[i][0] = fmaf(a[i], b.x, acc[i][0]);
                acc[i][1] = fmaf(a[i], b.y, acc[i][1]);
                acc[i][2] = fmaf(a[i], b.z, acc[i][2]);
                acc[i][3] = fmaf(a[i], b.w, acc[i][3]);
            }
        }
    }
#pragma unroll
    for (int i = 0; i < 8; i++) {
        float4 o;
        o.x = acc[i][0]; o.y = acc[i][1]; o.z = acc[i][2]; o.w = acc[i][3];
        *(float4*)&d_AB[(size_t)(mb + m0 + i) * 256 + nb + n0] = o;
    }
}

// ---------------- K4: per-edge gather + layernorm + FiLM + relu ----------------
// 1 warp processes 32 consecutive edges; lanes own 4 channels each.
// edge_indexes dtype probe: JAX without x64 downcasts jnp.int64 -> int32. For an
// int64 (LE) buffer, odd 32-bit words are zero high-words; for int32, words
// 262141/262143 are the two largest sorted values (~2^20, nonzero). Both probe
// offsets are in-bounds for either dtype (int32: 262144 words; int64: 524288).
__global__ void __launch_bounds__(256) k_film(const int* __restrict__ e32,
                                              const float* __restrict__ bf,
                                              float* __restrict__ out) {
    int gw = (blockIdx.x * 256 + threadIdx.x) >> 5;
    int lane = threadIdx.x & 31;
    long long base = (long long)gw * 32;

    int is64 = (e32[262143] == 0 && e32[262141] == 0) ? 1 : 0;
    int stride = is64 ? 2 : 1;

    float4 bfv = *(const float4*)(bf + lane * 4);
    int myi = e32[(size_t)(base + lane) * stride];   // index < 2^20, fits int32

    int gb = (int)(base >> 14);         // all 32 edges share batch slot (32 | 16384)
    float4 gv = *(const float4*)(d_gamma + gb * 128 + lane * 4);
    float4 bv = *(const float4*)(d_beta + gb * 128 + lane * 4);

#pragma unroll 4
    for (int e = 0; e < 32; e++) {
        int idx = __shfl_sync(0xffffffffu, myi, e);
        int v1 = idx >> 8;                                 // b*256 + i
        int v2 = ((idx >> 16) << 8) | (idx & 255);         // b*256 + j
        float4 xa = *(const float4*)(d_AB + (size_t)v1 * 256 + lane * 4);
        float4 xb = *(const float4*)(d_AB + (size_t)v2 * 256 + 128 + lane * 4);
        float4 x;
        x.x = xa.x + xb.x + bfv.x;
        x.y = xa.y + xb.y + bfv.y;
        x.z = xa.z + xb.z + bfv.z;
        x.w = xa.w + xb.w + bfv.w;

        float s  = (x.x + x.y) + (x.z + x.w);
        float s2 = x.x * x.x + x.y * x.y + x.z * x.z + x.w * x.w;
#pragma unroll
        for (int o = 16; o; o >>= 1) {
            s  += __shfl_xor_sync(0xffffffffu, s,  o);
            s2 += __shfl_xor_sync(0xffffffffu, s2, o);
        }
        float mean = s * 0.0078125f;                   // /128
        float var  = fmaf(s2, 0.0078125f, -mean * mean);
        float rs = rsqrtf(var + 1e-5f);

        float4 y;
        y.x = fmaxf(fmaf((x.x - mean) * rs, gv.x, bv.x), 0.f);
        y.y = fmaxf(fmaf((x.y - mean) * rs, gv.y, bv.y), 0.f);
        y.z = fmaxf(fmaf((x.z - mean) * rs, gv.z, bv.z), 0.f);
        y.w = fmaxf(fmaf((x.w - mean) * rs, gv.w, bv.w), 0.f);
        *(float4*)(out + (size_t)(base + e) * 128 + lane * 4) = y;
    }
}

// ---------------- launch ----------------
extern "C" void kernel_launch(void* const* d_in, const int* in_sizes, int n_in,
                              void* d_out, int out_size) {
    const float* node_feats   = (const float*)d_in[0];
    const float* cond_feats   = (const float*)d_in[1];
    const int* eidx32         = (const int*)d_in[2];
    const float* v_node       = (const float*)d_in[3];
    const float* g_node       = (const float*)d_in[4];
    const float* b_node       = (const float*)d_in[5];
    const float* v_cond       = (const float*)d_in[6];
    const float* g_cond       = (const float*)d_in[7];
    const float* b_cond       = (const float*)d_in[8];
    const float* w_film       = (const float*)d_in[9];
    const float* b_film       = (const float*)d_in[10];
    float* out = (float*)d_out;

    k_scales<<<48, 256>>>(v_node, g_node, v_cond, g_cond);          // 384 warps
    k_cond<<<512, 256>>>(cond_feats, v_cond, b_cond);               // 4096 warps
    k_nodes<<<128, 128>>>(node_feats, v_node, b_node);              // 4096x128 GEMM
    k_ab<<<dim3(128, 2), 128>>>(w_film);                            // 4096x256 GEMM
    k_film<<<1024, 256>>>(eidx32, b_film, out);                     // 262144 edges
}

// round 8
// speedup vs baseline: 1.0469x; 1.0469x over previous
// Re-bench of R6 source: R7 failure was a harness/broker device-acquisition
// flake ("device busy" at _harness_main.cu:253, before any kernel ran).
#include <cuda_runtime.h>

// ---------------- scratch (static device globals; no allocs) ----------------
__device__ float d_scale_n[128];
__device__ float d_nodes[4096 * 128];   // relu(node_feats @ w_n^T + b_node)
__device__ float d_AB[4096 * 256];      // [ nodes@W1^T | nodes@W2^T ]
__device__ float d_gamma[16 * 128];
__device__ float d_beta[16 * 128];

__device__ __forceinline__ float warp_sum(float v) {
#pragma unroll
    for (int o = 16; o; o >>= 1) v += __shfl_xor_sync(0xffffffffu, v, o);
    return v;
}

// ---------------- K1: weight-norm scales (node only; cond folded into k_cond) ----
// 128 warps, one per v_node row
__global__ void k_scales(const float* __restrict__ v_node, const float* __restrict__ g_node) {
    int w = (blockIdx.x * blockDim.x + threadIdx.x) >> 5;
    int lane = threadIdx.x & 31;
    const float* src = v_node + w * 512;
    float s = 0.f;
#pragma unroll
    for (int k = lane; k < 512; k += 32) { float v = src[k]; s += v * v; }
    s = warp_sum(s);
    if (lane == 0) d_scale_n[w] = g_node[w] * rsqrtf(s);
}

// ---------------- K_cond: gb = cond @ w_c^T + b_cond -> gamma/beta ----------------
// 4096 warps, one per (b, c). Weight-norm scale computed inline (free: same loads).
__global__ void k_cond(const float* __restrict__ cond, const float* __restrict__ vc,
                       const float* __restrict__ gc, const float* __restrict__ bc) {
    int w = (blockIdx.x << 3) + (threadIdx.x >> 5);
    int lane = threadIdx.x & 31;
    int b = w >> 8, c = w & 255;
    const float* cr = cond + b * 512;
    const float* vr = vc + c * 512;
    float s = 0.f, q = 0.f;
#pragma unroll
    for (int k = lane; k < 512; k += 32) {
        float v = vr[k];
        s = fmaf(cr[k], v, s);
        q = fmaf(v, v, q);
    }
#pragma unroll
    for (int o = 16; o; o >>= 1) {
        s += __shfl_xor_sync(0xffffffffu, s, o);
        q += __shfl_xor_sync(0xffffffffu, q, o);
    }
    if (lane == 0) {
        float r = fmaf(s, gc[c] * rsqrtf(q), bc[c]);
        if (c < 128) d_gamma[b * 128 + c] = r + 1.f;
        else         d_beta[b * 128 + (c - 128)] = r;
    }
}

// ---------------- GEMM tiles: BM=16, BN=128, BK=16, 128 threads, micro 4x4 ----------
// Software-pipelined: next chunk's global loads issued before the compute loop.

// K2: nodes = relu(node_feats @ (v_node*scale)^T + b_node).  4096x128, K=512.
__global__ void __launch_bounds__(128) k_nodes(const float* __restrict__ nf,
                                               const float* __restrict__ vn,
                                               const float* __restrict__ bn) {
    __shared__ float As[16][18];   // [k][m], padded
    __shared__ float Bs[16][128];  // [k][n]
    int tid = threadIdx.x;
    int mb = blockIdx.x * 16;

    int ar = tid & 15, ac = (tid >> 4) * 2;       // A: row, k-pair
    int br = tid >> 2, bk = (tid & 3) * 4;        // B: base row, k-group
    int m0 = (tid >> 5) * 4, n0 = (tid & 31) * 4;

    const float* Arow = nf + (size_t)(mb + ar) * 512 + ac;
    const float* B0 = vn + (size_t)(br +  0) * 512 + bk;
    const float* B1 = vn + (size_t)(br + 32) * 512 + bk;
    const float* B2 = vn + (size_t)(br + 64) * 512 + bk;
    const float* B3 = vn + (size_t)(br + 96) * 512 + bk;

    float2 aR = *(const float2*)Arow;
    float4 bR0 = *(const float4*)B0, bR1 = *(const float4*)B1;
    float4 bR2 = *(const float4*)B2, bR3 = *(const float4*)B3;

    float acc[4][4];
#pragma unroll
    for (int i = 0; i < 4; i++)
#pragma unroll
        for (int j = 0; j < 4; j++) acc[i][j] = 0.f;

#pragma unroll 1
    for (int c = 0; c < 32; c++) {
        __syncthreads();
        As[ac][ar] = aR.x; As[ac + 1][ar] = aR.y;
        Bs[bk + 0][br +  0] = bR0.x; Bs[bk + 1][br +  0] = bR0.y; Bs[bk + 2][br +  0] = bR0.z; Bs[bk + 3][br +  0] = bR0.w;
        Bs[bk + 0][br + 32] = bR1.x; Bs[bk + 1][br + 32] = bR1.y; Bs[bk + 2][br + 32] = bR1.z; Bs[bk + 3][br + 32] = bR1.w;
        Bs[bk + 0][br + 64] = bR2.x; Bs[bk + 1][br + 64] = bR2.y; Bs[bk + 2][br + 64] = bR2.z; Bs[bk + 3][br + 64] = bR2.w;
        Bs[bk + 0][br + 96] = bR3.x; Bs[bk + 1][br + 96] = bR3.y; Bs[bk + 2][br + 96] = bR3.z; Bs[bk + 3][br + 96] = bR3.w;
        __syncthreads();
        if (c < 31) {
            int k0 = (c + 1) * 16;
            aR  = *(const float2*)(Arow + k0);
            bR0 = *(const float4*)(B0 + k0);
            bR1 = *(const float4*)(B1 + k0);
            bR2 = *(const float4*)(B2 + k0);
            bR3 = *(const float4*)(B3 + k0);
        }
#pragma unroll
        for (int k = 0; k < 16; k++) {
            float a0 = As[k][m0 + 0], a1 = As[k][m0 + 1];
            float a2 = As[k][m0 + 2], a3 = As[k][m0 + 3];
            float4 b = *(const float4*)&Bs[k][n0];
            acc[0][0] = fmaf(a0, b.x, acc[0][0]); acc[0][1] = fmaf(a0, b.y, acc[0][1]);
            acc[0][2] = fmaf(a0, b.z, acc[0][2]); acc[0][3] = fmaf(a0, b.w, acc[0][3]);
            acc[1][0] = fmaf(a1, b.x, acc[1][0]); acc[1][1] = fmaf(a1, b.y, acc[1][1]);
            acc[1][2] = fmaf(a1, b.z, acc[1][2]); acc[1][3] = fmaf(a1, b.w, acc[1][3]);
            acc[2][0] = fmaf(a2, b.x, acc[2][0]); acc[2][1] = fmaf(a2, b.y, acc[2][1]);
            acc[2][2] = fmaf(a2, b.z, acc[2][2]); acc[2][3] = fmaf(a2, b.w, acc[2][3]);
            acc[3][0] = fmaf(a3, b.x, acc[3][0]); acc[3][1] = fmaf(a3, b.y, acc[3][1]);
            acc[3][2] = fmaf(a3, b.z, acc[3][2]); acc[3][3] = fmaf(a3, b.w, acc[3][3]);
        }
    }

    float4 sc = *(const float4*)&d_scale_n[n0];
    float4 bb = *(const float4*)&bn[n0];
#pragma unroll
    for (int i = 0; i < 4; i++) {
        float4 o;
        o.x = fmaxf(fmaf(acc[i][0], sc.x, bb.x), 0.f);
        o.y = fmaxf(fmaf(acc[i][1], sc.y, bb.y), 0.f);
        o.z = fmaxf(fmaf(acc[i][2], sc.z, bb.z), 0.f);
        o.w = fmaxf(fmaf(acc[i][3], sc.w, bb.w), 0.f);
        *(float4*)&d_nodes[(size_t)(mb + m0 + i) * 128 + n0] = o;
    }
}

// K3: AB = nodes @ [W1|W2]^T.  4096x256, K=128. blockIdx.y picks the 128-col half.
__global__ void __launch_bounds__(128) k_ab(const float* __restrict__ wf) {
    __shared__ float As[16][18];
    __shared__ float Bs[16][128];
    int tid = threadIdx.x;
    int mb = blockIdx.x * 16;
    int nb = blockIdx.y * 128;

    int ar = tid & 15, ac = (tid >> 4) * 2;
    int br = tid >> 2, bk = (tid & 3) * 4;
    int m0 = (tid >> 5) * 4, n0 = (tid & 31) * 4;

    const float* Arow = d_nodes + (size_t)(mb + ar) * 128 + ac;
    const float* wb = wf + nb;   // wb[row*256 + k] = wf[row][nb + k]
    const float* B0 = wb + (size_t)(br +  0) * 256 + bk;
    const float* B1 = wb + (size_t)(br + 32) * 256 + bk;
    const float* B2 = wb + (size_t)(br + 64) * 256 + bk;
    const float* B3 = wb + (size_t)(br + 96) * 256 + bk;

    float2 aR = *(const float2*)Arow;
    float4 bR0 = *(const float4*)B0, bR1 = *(const float4*)B1;
    float4 bR2 = *(const float4*)B2, bR3 = *(const float4*)B3;

    float acc[4][4];
#pragma unroll
    for (int i = 0; i < 4; i++)
#pragma unroll
        for (int j = 0; j < 4; j++) acc[i][j] = 0.f;

#pragma unroll 1
    for (int c = 0; c < 8; c++) {
        __syncthreads();
        As[ac][ar] = aR.x; As[ac + 1][ar] = aR.y;
        Bs[bk + 0][br +  0] = bR0.x; Bs[bk + 1][br +  0] = bR0.y; Bs[bk + 2][br +  0] = bR0.z; Bs[bk + 3][br +  0] = bR0.w;
        Bs[bk + 0][br + 32] = bR1.x; Bs[bk + 1][br + 32] = bR1.y; Bs[bk + 2][br + 32] = bR1.z; Bs[bk + 3][br + 32] = bR1.w;
        Bs[bk + 0][br + 64] = bR2.x; Bs[bk + 1][br + 64] = bR2.y; Bs[bk + 2][br + 64] = bR2.z; Bs[bk + 3][br + 64] = bR2.w;
        Bs[bk + 0][br + 96] = bR3.x; Bs[bk + 1][br + 96] = bR3.y; Bs[bk + 2][br + 96] = bR3.z; Bs[bk + 3][br + 96] = bR3.w;
        __syncthreads();
        if (c < 7) {
            int k0 = (c + 1) * 16;
            aR  = *(const float2*)(Arow + k0);
            bR0 = *(const float4*)(B0 + k0);
            bR1 = *(const float4*)(B1 + k0);
            bR2 = *(const float4*)(B2 + k0);
            bR3 = *(const float4*)(B3 + k0);
        }
#pragma unroll
        for (int k = 0; k < 16; k++) {
            float a0 = As[k][m0 + 0], a1 = As[k][m0 + 1];
            float a2 = As[k][m0 + 2], a3 = As[k][m0 + 3];
            float4 b = *(const float4*)&Bs[k][n0];
            acc[0][0] = fmaf(a0, b.x, acc[0][0]); acc[0][1] = fmaf(a0, b.y, acc[0][1]);
            acc[0][2] = fmaf(a0, b.z, acc[0][2]); acc[0][3] = fmaf(a0, b.w, acc[0][3]);
            acc[1][0] = fmaf(a1, b.x, acc[1][0]); acc[1][1] = fmaf(a1, b.y, acc[1][1]);
            acc[1][2] = fmaf(a1, b.z, acc[1][2]); acc[1][3] = fmaf(a1, b.w, acc[1][3]);
            acc[2][0] = fmaf(a2, b.x, acc[2][0]); acc[2][1] = fmaf(a2, b.y, acc[2][1]);
            acc[2][2] = fmaf(a2, b.z, acc[2][2]); acc[2][3] = fmaf(a2, b.w, acc[2][3]);
            acc[3][0] = fmaf(a3, b.x, acc[3][0]); acc[3][1] = fmaf(a3, b.y, acc[3][1]);
            acc[3][2] = fmaf(a3, b.z, acc[3][2]); acc[3][3] = fmaf(a3, b.w, acc[3][3]);
        }
    }
#pragma unroll
    for (int i = 0; i < 4; i++) {
        float4 o;
        o.x = acc[i][0]; o.y = acc[i][1]; o.z = acc[i][2]; o.w = acc[i][3];
        *(float4*)&d_AB[(size_t)(mb + m0 + i) * 256 + nb + n0] = o;
    }
}

// ---------------- K4: per-edge gather + layernorm + FiLM + relu ----------------
// 1 warp = 32 consecutive edges; lanes own 4 channels. Sorted edges => consecutive
// edges usually share the A-row (v1): cache xa, reload only on change.
// dtype probe: int64 (LE) buffer has zero odd words; int32 has nonzero tail words.
__global__ void __launch_bounds__(256) k_film(const int* __restrict__ e32,
                                              const float* __restrict__ bf,
                                              float* __restrict__ out) {
    int gw = (blockIdx.x * 256 + threadIdx.x) >> 5;
    int lane = threadIdx.x & 31;
    long long base = (long long)gw * 32;

    int stride = (e32[262143] == 0 && e32[262141] == 0) ? 2 : 1;

    float4 bfv = *(const float4*)(bf + lane * 4);
    int myi = e32[(size_t)(base + lane) * stride];

    int gb = (int)(base >> 14);   // position-batch (16384 edges per batch)
    float4 gv = *(const float4*)(d_gamma + gb * 128 + lane * 4);
    float4 bv = *(const float4*)(d_beta + gb * 128 + lane * 4);

    int prev = -1;
    float4 xa = make_float4(0.f, 0.f, 0.f, 0.f);

#pragma unroll 4
    for (int e = 0; e < 32; e++) {
        int idx = __shfl_sync(0xffffffffu, myi, e);
        int v1 = idx >> 8;                               // b*256 + i
        int v2 = ((idx >> 16) << 8) | (idx & 255);       // b*256 + j
        if (v1 != prev) {                                // warp-uniform branch
            xa = *(const float4*)(d_AB + (size_t)v1 * 256 + lane * 4);
            prev = v1;
        }
        float4 xb = *(const float4*)(d_AB + (size_t)v2 * 256 + 128 + lane * 4);
        float4 x;
        x.x = xa.x + xb.x + bfv.x;
        x.y = xa.y + xb.y + bfv.y;
        x.z = xa.z + xb.z + bfv.z;
        x.w = xa.w + xb.w + bfv.w;

        float s  = (x.x + x.y) + (x.z + x.w);
        float s2 = x.x * x.x + x.y * x.y + x.z * x.z + x.w * x.w;
#pragma unroll
        for (int o = 16; o; o >>= 1) {
            s  += __shfl_xor_sync(0xffffffffu, s,  o);
            s2 += __shfl_xor_sync(0xffffffffu, s2, o);
        }
        float mean = s * 0.0078125f;                    // /128
        float var  = fmaf(s2, 0.0078125f, -mean * mean);
        float rs = rsqrtf(var + 1e-5f);

        float4 y;
        y.x = fmaxf(fmaf((x.x - mean) * rs, gv.x, bv.x), 0.f);
        y.y = fmaxf(fmaf((x.y - mean) * rs, gv.y, bv.y), 0.f);
        y.z = fmaxf(fmaf((x.z - mean) * rs, gv.z, bv.z), 0.f);
        y.w = fmaxf(fmaf((x.w - mean) * rs, gv.w, bv.w), 0.f);
        __stcs((float4*)(out + (size_t)(base + e) * 128 + lane * 4), y);  // streaming store
    }
}

// ---------------- launch ----------------
extern "C" void kernel_launch(void* const* d_in, const int* in_sizes, int n_in,
                              void* d_out, int out_size) {
    const float* node_feats   = (const float*)d_in[0];
    const float* cond_feats   = (const float*)d_in[1];
    const int* eidx32         = (const int*)d_in[2];
    const float* v_node       = (const float*)d_in[3];
    const float* g_node       = (const float*)d_in[4];
    const float* b_node       = (const float*)d_in[5];
    const float* v_cond       = (const float*)d_in[6];
    const float* g_cond       = (const float*)d_in[7];
    const float* b_cond       = (const float*)d_in[8];
    const float* w_film       = (const float*)d_in[9];
    const float* b_film       = (const float*)d_in[10];
    float* out = (float*)d_out;

    k_scales<<<16, 256>>>(v_node, g_node);                            // 128 warps
    k_cond<<<512, 256>>>(cond_feats, v_cond, g_cond, b_cond);         // 4096 warps
    k_nodes<<<256, 128>>>(node_feats, v_node, b_node);                // 4096x128, K=512
    k_ab<<<dim3(256, 2), 128>>>(w_film);                              // 4096x256, K=128
    k_film<<<1024, 256>>>(eidx32, b_film, out);                       // 262144 edges
}

// round 10
// speedup vs baseline: 1.1744x; 1.1218x over previous
// Re-bench of R8 fused-kernel source: R9 failed at the broker/container level
// ("GB300 container failed twice") before any kernel ran. No source changes.
#include <cuda_runtime.h>

// ---------------- scratch (static device globals; no allocs) ----------------
__device__ float d_scale_n[128];
__device__ float d_AB[4096 * 256];      // [ nodes@W1^T | nodes@W2^T ]
__device__ float d_gamma[16 * 128];
__device__ float d_beta[16 * 128];

__device__ __forceinline__ float warp_sum(float v) {
#pragma unroll
    for (int o = 16; o; o >>= 1) v += __shfl_xor_sync(0xffffffffu, v, o);
    return v;
}

// ---------------- K1: weight-norm scales for v_node ----------------
__global__ void k_scales(const float* __restrict__ v_node, const float* __restrict__ g_node) {
    int w = (blockIdx.x * blockDim.x + threadIdx.x) >> 5;
    int lane = threadIdx.x & 31;
    const float* src = v_node + w * 512;
    float s = 0.f;
#pragma unroll
    for (int k = lane; k < 512; k += 32) { float v = src[k]; s += v * v; }
    s = warp_sum(s);
    if (lane == 0) d_scale_n[w] = g_node[w] * rsqrtf(s);
}

// ---------------- K_cond: one warp per channel c; cond staged in smem --------
// grid 64 x 128 threads = 256 warps = 256 channels. v-row in regs, 16 dots each.
__global__ void __launch_bounds__(128) k_cond(const float* __restrict__ cond,
                                              const float* __restrict__ vc,
                                              const float* __restrict__ gc,
                                              const float* __restrict__ bc) {
    __shared__ float cs[16 * 512];   // 32 KB
    int tid = threadIdx.x;
    for (int i = tid; i < 16 * 512 / 4; i += 128)
        ((float4*)cs)[i] = ((const float4*)cond)[i];
    __syncthreads();

    int c = blockIdx.x * 4 + (tid >> 5);
    int lane = tid & 31;
    const float* vr = vc + (size_t)c * 512;

    float v[16];
    float q = 0.f;
#pragma unroll
    for (int i = 0; i < 16; i++) { v[i] = vr[lane + 32 * i]; q = fmaf(v[i], v[i], q); }
    q = warp_sum(q);
    float sc = gc[c] * rsqrtf(q);
    float bias = bc[c];

#pragma unroll
    for (int b = 0; b < 16; b++) {
        const float* cr = cs + b * 512;
        float s = 0.f;
#pragma unroll
        for (int i = 0; i < 16; i++) s = fmaf(cr[lane + 32 * i], v[i], s);
        s = warp_sum(s);
        if (lane == 0) {
            float r = fmaf(s, sc, bias);
            if (c < 128) d_gamma[b * 128 + c] = r + 1.f;
            else         d_beta[b * 128 + (c - 128)] = r;
        }
    }
}

// ---------------- Fused GEMM: nodes tile -> AB tile ----------------
// grid 128 x 128 threads. BM=32 rows per block.
// Phase 1: N1(32x128) = relu(nf[32,512] @ (vn*scale)^T + bn), microtile 8x4.
// Phase 2: AB(32x256)  = N1 @ Wt^T (K=128), microtile 8x8, N1 kept in smem.
__global__ void __launch_bounds__(128) k_fused(const float* __restrict__ nf,
                                               const float* __restrict__ vn,
                                               const float* __restrict__ bn,
                                               const float* __restrict__ wf) {
    __shared__ float As1[16][32];    // [k][m]  2 KB
    __shared__ float Bs1[16][128];   // [k][n]  8 KB
    __shared__ float Ns[128][33];    // [k2][m] transposed nodes tile, padded (16.5 KB)
    __shared__ float Bs2[16][256];   // [k][n]  16 KB

    int tid = threadIdx.x;
    int mb = blockIdx.x * 32;
    int m0 = (tid >> 5) * 8;         // warp-uniform
    int n0 = (tid & 31) * 4;         // phase-1 col group

    // -------- Phase 1 --------
    int ar = tid & 31, ac = (tid >> 5) * 4;       // A loader: row, k-offset
    int br = tid >> 2, bk = (tid & 3) * 4;        // B loader

    const float* Arow = nf + (size_t)(mb + ar) * 512 + ac;
    const float* B0 = vn + (size_t)(br +  0) * 512 + bk;
    const float* B1 = vn + (size_t)(br + 32) * 512 + bk;
    const float* B2 = vn + (size_t)(br + 64) * 512 + bk;
    const float* B3 = vn + (size_t)(br + 96) * 512 + bk;

    float4 aR = *(const float4*)Arow;
    float4 bR0 = *(const float4*)B0, bR1 = *(const float4*)B1;
    float4 bR2 = *(const float4*)B2, bR3 = *(const float4*)B3;

    float acc[8][4];
#pragma unroll
    for (int i = 0; i < 8; i++)
#pragma unroll
        for (int j = 0; j < 4; j++) acc[i][j] = 0.f;

#pragma unroll 1
    for (int c = 0; c < 32; c++) {
        __syncthreads();
        As1[ac + 0][ar] = aR.x; As1[ac + 1][ar] = aR.y;
        As1[ac + 2][ar] = aR.z; As1[ac + 3][ar] = aR.w;
        Bs1[bk + 0][br +  0] = bR0.x; Bs1[bk + 1][br +  0] = bR0.y; Bs1[bk + 2][br +  0] = bR0.z; Bs1[bk + 3][br +  0] = bR0.w;
        Bs1[bk + 0][br + 32] = bR1.x; Bs1[bk + 1][br + 32] = bR1.y; Bs1[bk + 2][br + 32] = bR1.z; Bs1[bk + 3][br + 32] = bR1.w;
        Bs1[bk + 0][br + 64] = bR2.x; Bs1[bk + 1][br + 64] = bR2.y; Bs1[bk + 2][br + 64] = bR2.z; Bs1[bk + 3][br + 64] = bR2.w;
        Bs1[bk + 0][br + 96] = bR3.x; Bs1[bk + 1][br + 96] = bR3.y; Bs1[bk + 2][br + 96] = bR3.z; Bs1[bk + 3][br + 96] = bR3.w;
        __syncthreads();
        if (c < 31) {
            int k0 = (c + 1) * 16;
            aR  = *(const float4*)(Arow + k0);
            bR0 = *(const float4*)(B0 + k0);
            bR1 = *(const float4*)(B1 + k0);
            bR2 = *(const float4*)(B2 + k0);
            bR3 = *(const float4*)(B3 + k0);
        }
#pragma unroll
        for (int k = 0; k < 16; k++) {
            float4 aLo = *(const float4*)&As1[k][m0];        // broadcast within warp
            float4 aHi = *(const float4*)&As1[k][m0 + 4];
            float4 b = *(const float4*)&Bs1[k][n0];
            float a[8] = {aLo.x, aLo.y, aLo.z, aLo.w, aHi.x, aHi.y, aHi.z, aHi.w};
#pragma unroll
            for (int i = 0; i < 8; i++) {
                acc[i][0] = fmaf(a[i], b.x, acc[i][0]);
                acc[i][1] = fmaf(a[i], b.y, acc[i][1]);
                acc[i][2] = fmaf(a[i], b.z, acc[i][2]);
                acc[i][3] = fmaf(a[i], b.w, acc[i][3]);
            }
        }
    }

    // epilogue: relu(acc*scale+bias) -> Ns[n][m] (transposed for phase-2 K access)
    {
        float4 sc4 = *(const float4*)&d_scale_n[n0];
        float4 bb4 = *(const float4*)&bn[n0];
        __syncthreads();   // done with As1/Bs1 region timing; ensure all reads finished
#pragma unroll
        for (int i = 0; i < 8; i++) {
            Ns[n0 + 0][m0 + i] = fmaxf(fmaf(acc[i][0], sc4.x, bb4.x), 0.f);
            Ns[n0 + 1][m0 + i] = fmaxf(fmaf(acc[i][1], sc4.y, bb4.y), 0.f);
            Ns[n0 + 2][m0 + i] = fmaxf(fmaf(acc[i][2], sc4.z, bb4.z), 0.f);
            Ns[n0 + 3][m0 + i] = fmaxf(fmaf(acc[i][3], sc4.w, bb4.w), 0.f);
        }
    }
    __syncthreads();

    // -------- Phase 2: AB(32x256) = Ns^T(32x128) @ Wt^T, K=128 --------
    // Wt[n][k]: n<128 -> wf[n][k]; n>=128 -> wf[n-128][128+k]
    int n2 = (tid & 31) * 8;                 // output col group (8 cols)
    int br2 = tid >> 2, bk2 = (tid & 3) * 4; // B loader
    int roff[8];
#pragma unroll
    for (int j = 0; j < 8; j++) {
        int n = br2 + 32 * j;
        roff[j] = (j < 4) ? n * 256 + bk2 : (n - 128) * 256 + 128 + bk2;
    }

    float4 w0 = *(const float4*)(wf + roff[0]);
    float4 w1 = *(const float4*)(wf + roff[1]);
    float4 w2 = *(const float4*)(wf + roff[2]);
    float4 w3 = *(const float4*)(wf + roff[3]);
    float4 w4 = *(const float4*)(wf + roff[4]);
    float4 w5 = *(const float4*)(wf + roff[5]);
    float4 w6 = *(const float4*)(wf + roff[6]);
    float4 w7 = *(const float4*)(wf + roff[7]);

    float acc2[8][8];
#pragma unroll
    for (int i = 0; i < 8; i++)
#pragma unroll
        for (int j = 0; j < 8; j++) acc2[i][j] = 0.f;

#pragma unroll 1
    for (int c = 0; c < 8; c++) {
        __syncthreads();
        Bs2[bk2 + 0][br2 +   0] = w0.x; Bs2[bk2 + 1][br2 +   0] = w0.y; Bs2[bk2 + 2][br2 +   0] = w0.z; Bs2[bk2 + 3][br2 +   0] = w0.w;
        Bs2[bk2 + 0][br2 +  32] = w1.x; Bs2[bk2 + 1][br2 +  32] = w1.y; Bs2[bk2 + 2][br2 +  32] = w1.z; Bs2[bk2 + 3][br2 +  32] = w1.w;
        Bs2[bk2 + 0][br2 +  64] = w2.x; Bs2[bk2 + 1][br2 +  64] = w2.y; Bs2[bk2 + 2][br2 +  64] = w2.z; Bs2[bk2 + 3][br2 +  64] = w2.w;
        Bs2[bk2 + 0][br2 +  96] = w3.x; Bs2[bk2 + 1][br2 +  96] = w3.y; Bs2[bk2 + 2][br2 +  96] = w3.z; Bs2[bk2 + 3][br2 +  96] = w3.w;
        Bs2[bk2 + 0][br2 + 128] = w4.x; Bs2[bk2 + 1][br2 + 128] = w4.y; Bs2[bk2 + 2][br2 + 128] = w4.z; Bs2[bk2 + 3][br2 + 128] = w4.w;
        Bs2[bk2 + 0][br2 + 160] = w5.x; Bs2[bk2 + 1][br2 + 160] = w5.y; Bs2[bk2 + 2][br2 + 160] = w5.z; Bs2[bk2 + 3][br2 + 160] = w5.w;
        Bs2[bk2 + 0][br2 + 192] = w6.x; Bs2[bk2 + 1][br2 + 192] = w6.y; Bs2[bk2 + 2][br2 + 192] = w6.z; Bs2[bk2 + 3][br2 + 192] = w6.w;
        Bs2[bk2 + 0][br2 + 224] = w7.x; Bs2[bk2 + 1][br2 + 224] = w7.y; Bs2[bk2 + 2][br2 + 224] = w7.z; Bs2[bk2 + 3][br2 + 224] = w7.w;
        __syncthreads();
        if (c < 7) {
            int k0 = (c + 1) * 16;
            w0 = *(const float4*)(wf + roff[0] + k0);
            w1 = *(const float4*)(wf + roff[1] + k0);
            w2 = *(const float4*)(wf + roff[2] + k0);
            w3 = *(const float4*)(wf + roff[3] + k0);
            w4 = *(const float4*)(wf + roff[4] + k0);
            w5 = *(const float4*)(wf + roff[5] + k0);
            w6 = *(const float4*)(wf + roff[6] + k0);
            w7 = *(const float4*)(wf + roff[7] + k0);
        }
        int kbase = c * 16;
#pragma unroll
        for (int k = 0; k < 16; k++) {
            const float* nrow = &Ns[kbase + k][m0];   // broadcast within warp
            float4 bLo = *(const float4*)&Bs2[k][n2];
            float4 bHi = *(const float4*)&Bs2[k][n2 + 4];
            float b[8] = {bLo.x, bLo.y, bLo.z, bLo.w, bHi.x, bHi.y, bHi.z, bHi.w};
#pragma unroll
            for (int i = 0; i < 8; i++) {
                float a = nrow[i];
#pragma unroll
                for (int j = 0; j < 8; j++) acc2[i][j] = fmaf(a, b[j], acc2[i][j]);
            }
        }
    }

#pragma unroll
    for (int i = 0; i < 8; i++) {
        float4 o0, o1;
        o0.x = acc2[i][0]; o0.y = acc2[i][1]; o0.z = acc2[i][2]; o0.w = acc2[i][3];
        o1.x = acc2[i][4]; o1.y = acc2[i][5]; o1.z = acc2[i][6]; o1.w = acc2[i][7];
        float* dst = &d_AB[(size_t)(mb + m0 + i) * 256 + n2];
        *(float4*)dst = o0;
        *(float4*)(dst + 4) = o1;
    }
}

// ---------------- K4: per-edge gather + layernorm + FiLM + relu ----------------
// 1 warp = 32 consecutive edges; lanes own 4 channels. Sorted edges => consecutive
// edges usually share the A-row (v1): cache xa, reload only on change.
// dtype probe: int64 (LE) buffer has zero odd words; int32 has nonzero tail words.
__global__ void __launch_bounds__(256) k_film(const int* __restrict__ e32,
                                              const float* __restrict__ bf,
                                              float* __restrict__ out) {
    int gw = (blockIdx.x * 256 + threadIdx.x) >> 5;
    int lane = threadIdx.x & 31;
    long long base = (long long)gw * 32;

    int stride = (e32[262143] == 0 && e32[262141] == 0) ? 2 : 1;

    float4 bfv = *(const float4*)(bf + lane * 4);
    int myi = e32[(size_t)(base + lane) * stride];

    int gb = (int)(base >> 14);   // position-batch (16384 edges per batch)
    float4 gv = *(const float4*)(d_gamma + gb * 128 + lane * 4);
    float4 bv = *(const float4*)(d_beta + gb * 128 + lane * 4);

    int prev = -1;
    float4 xa = make_float4(0.f, 0.f, 0.f, 0.f);

#pragma unroll 4
    for (int e = 0; e < 32; e++) {
        int idx = __shfl_sync(0xffffffffu, myi, e);
        int v1 = idx >> 8;                               // b*256 + i
        int v2 = ((idx >> 16) << 8) | (idx & 255);       // b*256 + j
        if (v1 != prev) {                                // warp-uniform branch
            xa = *(const float4*)(d_AB + (size_t)v1 * 256 + lane * 4);
            prev = v1;
        }
        float4 xb = *(const float4*)(d_AB + (size_t)v2 * 256 + 128 + lane * 4);
        float4 x;
        x.x = xa.x + xb.x + bfv.x;
        x.y = xa.y + xb.y + bfv.y;
        x.z = xa.z + xb.z + bfv.z;
        x.w = xa.w + xb.w + bfv.w;

        float s  = (x.x + x.y) + (x.z + x.w);
        float s2 = x.x * x.x + x.y * x.y + x.z * x.z + x.w * x.w;
#pragma unroll
        for (int o = 16; o; o >>= 1) {
            s  += __shfl_xor_sync(0xffffffffu, s,  o);
            s2 += __shfl_xor_sync(0xffffffffu, s2, o);
        }
        float mean = s * 0.0078125f;                    // /128
        float var  = fmaf(s2, 0.0078125f, -mean * mean);
        float rs = rsqrtf(var + 1e-5f);

        float4 y;
        y.x = fmaxf(fmaf((x.x - mean) * rs, gv.x, bv.x), 0.f);
        y.y = fmaxf(fmaf((x.y - mean) * rs, gv.y, bv.y), 0.f);
        y.z = fmaxf(fmaf((x.z - mean) * rs, gv.z, bv.z), 0.f);
        y.w = fmaxf(fmaf((x.w - mean) * rs, gv.w, bv.w), 0.f);
        __stcs((float4*)(out + (size_t)(base + e) * 128 + lane * 4), y);  // streaming store
    }
}

// ---------------- launch ----------------
extern "C" void kernel_launch(void* const* d_in, const int* in_sizes, int n_in,
                              void* d_out, int out_size) {
    const float* node_feats   = (const float*)d_in[0];
    const float* cond_feats   = (const float*)d_in[1];
    const int* eidx32         = (const int*)d_in[2];
    const float* v_node       = (const float*)d_in[3];
    const float* g_node       = (const float*)d_in[4];
    const float* b_node       = (const float*)d_in[5];
    const float* v_cond       = (const float*)d_in[6];
    const float* g_cond       = (const float*)d_in[7];
    const float* b_cond       = (const float*)d_in[8];
    const float* w_film       = (const float*)d_in[9];
    const float* b_film       = (const float*)d_in[10];
    float* out = (float*)d_out;

    k_scales<<<16, 256>>>(v_node, g_node);                              // 128 warps
    k_cond<<<64, 128>>>(cond_feats, v_cond, g_cond, b_cond);            // 256 warps
    k_fused<<<128, 128>>>(node_feats, v_node, b_node, w_film);          // both GEMMs
    k_film<<<1024, 256>>>(eidx32, b_film, out);                         // 262144 edges
}

// round 12
// speedup vs baseline: 1.1880x; 1.0115x over previous
#include <cuda_runtime.h>

// ---------------- scratch (static device globals; no allocs) ----------------
__device__ float d_scale_n[128];
__device__ float d_AB[4096 * 256];      // [ (nodes@W1^T + b_film) | nodes@W2^T ]
__device__ float d_sumA[4096];          // row sums of A half (bf folded)
__device__ float d_sumB[4096];          // row sums of B half
__device__ float d_gamma[16 * 128];
__device__ float d_beta[16 * 128];

__device__ __forceinline__ float warp_sum(float v) {
#pragma unroll
    for (int o = 16; o; o >>= 1) v += __shfl_xor_sync(0xffffffffu, v, o);
    return v;
}

// ---------------- K1: weight-norm scales for v_node ----------------
__global__ void k_scales(const float* __restrict__ v_node, const float* __restrict__ g_node) {
    int w = (blockIdx.x * blockDim.x + threadIdx.x) >> 5;
    int lane = threadIdx.x & 31;
    const float* src = v_node + w * 512;
    float s = 0.f;
#pragma unroll
    for (int k = lane; k < 512; k += 32) { float v = src[k]; s += v * v; }
    s = warp_sum(s);
    if (lane == 0) d_scale_n[w] = g_node[w] * rsqrtf(s);
}

// ---------------- K_cond: one warp per channel c; cond staged in smem --------
__global__ void __launch_bounds__(128) k_cond(const float* __restrict__ cond,
                                              const float* __restrict__ vc,
                                              const float* __restrict__ gc,
                                              const float* __restrict__ bc) {
    __shared__ float cs[16 * 512];   // 32 KB
    int tid = threadIdx.x;
    for (int i = tid; i < 16 * 512 / 4; i += 128)
        ((float4*)cs)[i] = ((const float4*)cond)[i];
    __syncthreads();

    int c = blockIdx.x * 4 + (tid >> 5);
    int lane = tid & 31;
    const float* vr = vc + (size_t)c * 512;

    float v[16];
    float q = 0.f;
#pragma unroll
    for (int i = 0; i < 16; i++) { v[i] = vr[lane + 32 * i]; q = fmaf(v[i], v[i], q); }
    q = warp_sum(q);
    float sc = gc[c] * rsqrtf(q);
    float bias = bc[c];

#pragma unroll
    for (int b = 0; b < 16; b++) {
        const float* cr = cs + b * 512;
        float s = 0.f;
#pragma unroll
        for (int i = 0; i < 16; i++) s = fmaf(cr[lane + 32 * i], v[i], s);
        s = warp_sum(s);
        if (lane == 0) {
            float r = fmaf(s, sc, bias);
            if (c < 128) d_gamma[b * 128 + c] = r + 1.f;
            else         d_beta[b * 128 + (c - 128)] = r;
        }
    }
}

// ---------------- Fused GEMM: nodes tile -> AB tile (+ bf fold + row sums) ----
// grid 128 x 128 threads. BM=32 rows per block.
__global__ void __launch_bounds__(128) k_fused(const float* __restrict__ nf,
                                               const float* __restrict__ vn,
                                               const float* __restrict__ bn,
                                               const float* __restrict__ wf,
                                               const float* __restrict__ bf) {
    __shared__ float As1[16][32];    // [k][m]
    __shared__ float Bs1[16][128];   // [k][n]
    __shared__ float Ns[128][33];    // [k2][m] transposed nodes tile, padded
    __shared__ float Bs2[16][256];   // [k][n]

    int tid = threadIdx.x;
    int mb = blockIdx.x * 32;
    int m0 = (tid >> 5) * 8;         // warp-uniform
    int n0 = (tid & 31) * 4;         // phase-1 col group

    // -------- Phase 1: N1(32x128) = relu(nf @ (vn*scale)^T + bn) --------
    int ar = tid & 31, ac = (tid >> 5) * 4;
    int br = tid >> 2, bk = (tid & 3) * 4;

    const float* Arow = nf + (size_t)(mb + ar) * 512 + ac;
    const float* B0 = vn + (size_t)(br +  0) * 512 + bk;
    const float* B1 = vn + (size_t)(br + 32) * 512 + bk;
    const float* B2 = vn + (size_t)(br + 64) * 512 + bk;
    const float* B3 = vn + (size_t)(br + 96) * 512 + bk;

    float4 aR = *(const float4*)Arow;
    float4 bR0 = *(const float4*)B0, bR1 = *(const float4*)B1;
    float4 bR2 = *(const float4*)B2, bR3 = *(const float4*)B3;

    float acc[8][4];
#pragma unroll
    for (int i = 0; i < 8; i++)
#pragma unroll
        for (int j = 0; j < 4; j++) acc[i][j] = 0.f;

#pragma unroll 1
    for (int c = 0; c < 32; c++) {
        __syncthreads();
        As1[ac + 0][ar] = aR.x; As1[ac + 1][ar] = aR.y;
        As1[ac + 2][ar] = aR.z; As1[ac + 3][ar] = aR.w;
        Bs1[bk + 0][br +  0] = bR0.x; Bs1[bk + 1][br +  0] = bR0.y; Bs1[bk + 2][br +  0] = bR0.z; Bs1[bk + 3][br +  0] = bR0.w;
        Bs1[bk + 0][br + 32] = bR1.x; Bs1[bk + 1][br + 32] = bR1.y; Bs1[bk + 2][br + 32] = bR1.z; Bs1[bk + 3][br + 32] = bR1.w;
        Bs1[bk + 0][br + 64] = bR2.x; Bs1[bk + 1][br + 64] = bR2.y; Bs1[bk + 2][br + 64] = bR2.z; Bs1[bk + 3][br + 64] = bR2.w;
        Bs1[bk + 0][br + 96] = bR3.x; Bs1[bk + 1][br + 96] = bR3.y; Bs1[bk + 2][br + 96] = bR3.z; Bs1[bk + 3][br + 96] = bR3.w;
        __syncthreads();
        if (c < 31) {
            int k0 = (c + 1) * 16;
            aR  = *(const float4*)(Arow + k0);
            bR0 = *(const float4*)(B0 + k0);
            bR1 = *(const float4*)(B1 + k0);
            bR2 = *(const float4*)(B2 + k0);
            bR3 = *(const float4*)(B3 + k0);
        }
#pragma unroll
        for (int k = 0; k < 16; k++) {
            float4 aLo = *(const float4*)&As1[k][m0];        // broadcast within warp
            float4 aHi = *(const float4*)&As1[k][m0 + 4];
            float4 b = *(const float4*)&Bs1[k][n0];
            float a[8] = {aLo.x, aLo.y, aLo.z, aLo.w, aHi.x, aHi.y, aHi.z, aHi.w};
#pragma unroll
            for (int i = 0; i < 8; i++) {
                acc[i][0] = fmaf(a[i], b.x, acc[i][0]);
                acc[i][1] = fmaf(a[i], b.y, acc[i][1]);
                acc[i][2] = fmaf(a[i], b.z, acc[i][2]);
                acc[i][3] = fmaf(a[i], b.w, acc[i][3]);
            }
        }
    }

    // epilogue: relu(acc*scale+bias) -> Ns[n][m]
    {
        float4 sc4 = *(const float4*)&d_scale_n[n0];
        float4 bb4 = *(const float4*)&bn[n0];
        __syncthreads();
#pragma unroll
        for (int i = 0; i < 8; i++) {
            Ns[n0 + 0][m0 + i] = fmaxf(fmaf(acc[i][0], sc4.x, bb4.x), 0.f);
            Ns[n0 + 1][m0 + i] = fmaxf(fmaf(acc[i][1], sc4.y, bb4.y), 0.f);
            Ns[n0 + 2][m0 + i] = fmaxf(fmaf(acc[i][2], sc4.z, bb4.z), 0.f);
            Ns[n0 + 3][m0 + i] = fmaxf(fmaf(acc[i][3], sc4.w, bb4.w), 0.f);
        }
    }
    __syncthreads();

    // -------- Phase 2: AB(32x256) = Ns^T @ Wt^T, K=128 --------
    int lane = tid & 31;
    int n2 = lane * 8;                       // output col group (8 cols)
    int br2 = tid >> 2, bk2 = (tid & 3) * 4; // B loader
    int roff[8];
#pragma unroll
    for (int j = 0; j < 8; j++) {
        int n = br2 + 32 * j;
        roff[j] = (j < 4) ? n * 256 + bk2 : (n - 128) * 256 + 128 + bk2;
    }

    float4 w0 = *(const float4*)(wf + roff[0]);
    float4 w1 = *(const float4*)(wf + roff[1]);
    float4 w2 = *(const float4*)(wf + roff[2]);
    float4 w3 = *(const float4*)(wf + roff[3]);
    float4 w4 = *(const float4*)(wf + roff[4]);
    float4 w5 = *(const float4*)(wf + roff[5]);
    float4 w6 = *(const float4*)(wf + roff[6]);
    float4 w7 = *(const float4*)(wf + roff[7]);

    float acc2[8][8];
#pragma unroll
    for (int i = 0; i < 8; i++)
#pragma unroll
        for (int j = 0; j < 8; j++) acc2[i][j] = 0.f;

#pragma unroll 1
    for (int c = 0; c < 8; c++) {
        __syncthreads();
        Bs2[bk2 + 0][br2 +   0] = w0.x; Bs2[bk2 + 1][br2 +   0] = w0.y; Bs2[bk2 + 2][br2 +   0] = w0.z; Bs2[bk2 + 3][br2 +   0] = w0.w;
        Bs2[bk2 + 0][br2 +  32] = w1.x; Bs2[bk2 + 1][br2 +  32] = w1.y; Bs2[bk2 + 2][br2 +  32] = w1.z; Bs2[bk2 + 3][br2 +  32] = w1.w;
        Bs2[bk2 + 0][br2 +  64] = w2.x; Bs2[bk2 + 1][br2 +  64] = w2.y; Bs2[bk2 + 2][br2 +  64] = w2.z; Bs2[bk2 + 3][br2 +  64] = w2.w;
        Bs2[bk2 + 0][br2 +  96] = w3.x; Bs2[bk2 + 1][br2 +  96] = w3.y; Bs2[bk2 + 2][br2 +  96] = w3.z; Bs2[bk2 + 3][br2 +  96] = w3.w;
        Bs2[bk2 + 0][br2 + 128] = w4.x; Bs2[bk2 + 1][br2 + 128] = w4.y; Bs2[bk2 + 2][br2 + 128] = w4.z; Bs2[bk2 + 3][br2 + 128] = w4.w;
        Bs2[bk2 + 0][br2 + 160] = w5.x; Bs2[bk2 + 1][br2 + 160] = w5.y; Bs2[bk2 + 2][br2 + 160] = w5.z; Bs2[bk2 + 3][br2 + 160] = w5.w;
        Bs2[bk2 + 0][br2 + 192] = w6.x; Bs2[bk2 + 1][br2 + 192] = w6.y; Bs2[bk2 + 2][br2 + 192] = w6.z; Bs2[bk2 + 3][br2 + 192] = w6.w;
        Bs2[bk2 + 0][br2 + 224] = w7.x; Bs2[bk2 + 1][br2 + 224] = w7.y; Bs2[bk2 + 2][br2 + 224] = w7.z; Bs2[bk2 + 3][br2 + 224] = w7.w;
        __syncthreads();
        if (c < 7) {
            int k0 = (c + 1) * 16;
            w0 = *(const float4*)(wf + roff[0] + k0);
            w1 = *(const float4*)(wf + roff[1] + k0);
            w2 = *(const float4*)(wf + roff[2] + k0);
            w3 = *(const float4*)(wf + roff[3] + k0);
            w4 = *(const float4*)(wf + roff[4] + k0);
            w5 = *(const float4*)(wf + roff[5] + k0);
            w6 = *(const float4*)(wf + roff[6] + k0);
            w7 = *(const float4*)(wf + roff[7] + k0);
        }
        int kbase = c * 16;
#pragma unroll
        for (int k = 0; k < 16; k++) {
            const float* nrow = &Ns[kbase + k][m0];   // broadcast within warp
            float4 bLo = *(const float4*)&Bs2[k][n2];
            float4 bHi = *(const float4*)&Bs2[k][n2 + 4];
            float b[8] = {bLo.x, bLo.y, bLo.z, bLo.w, bHi.x, bHi.y, bHi.z, bHi.w};
#pragma unroll
            for (int i = 0; i < 8; i++) {
                float a = nrow[i];
#pragma unroll
                for (int j = 0; j < 8; j++) acc2[i][j] = fmaf(a, b[j], acc2[i][j]);
            }
        }
    }

    // -------- Epilogue: fold b_film into A half, write AB, emit row sums --------
    // lanes 0..15 hold cols [0,128) (A half); lanes 16..31 hold cols [128,256) (B half)
    if (lane < 16) {
        float4 f0 = *(const float4*)(bf + n2);
        float4 f1 = *(const float4*)(bf + n2 + 4);
#pragma unroll
        for (int i = 0; i < 8; i++) {
            acc2[i][0] += f0.x; acc2[i][1] += f0.y; acc2[i][2] += f0.z; acc2[i][3] += f0.w;
            acc2[i][4] += f1.x; acc2[i][5] += f1.y; acc2[i][6] += f1.z; acc2[i][7] += f1.w;
        }
    }

#pragma unroll
    for (int i = 0; i < 8; i++) {
        float4 o0, o1;
        o0.x = acc2[i][0]; o0.y = acc2[i][1]; o0.z = acc2[i][2]; o0.w = acc2[i][3];
        o1.x = acc2[i][4]; o1.y = acc2[i][5]; o1.z = acc2[i][6]; o1.w = acc2[i][7];
        float* dst = &d_AB[(size_t)(mb + m0 + i) * 256 + n2];
        *(float4*)dst = o0;
        *(float4*)(dst + 4) = o1;

        // row sum within each 16-lane half (xor <= 8 keeps halves separate)
        float rsum = ((acc2[i][0] + acc2[i][1]) + (acc2[i][2] + acc2[i][3]))
                   + ((acc2[i][4] + acc2[i][5]) + (acc2[i][6] + acc2[i][7]));
#pragma unroll
        for (int o = 8; o; o >>= 1) rsum += __shfl_xor_sync(0xffffffffu, rsum, o);
        if (lane == 0)  d_sumA[mb + m0 + i] = rsum;
        if (lane == 16) d_sumB[mb + m0 + i] = rsum;
    }
}

// ---------------- K4: per-edge gather + layernorm + FiLM + relu ----------------
// Half-warp per edge: 16 lanes x 8 channels; 2 edges in flight per warp.
// mean is precomputed (d_sumA/d_sumB); only the variance needs a (shared) 4-level
// reduction. A-row cached in registers keyed on v1 (sorted edges, run-length ~64).
// dtype probe: int64 (LE) buffer has zero odd words; int32 has nonzero tail words.
__global__ void __launch_bounds__(256) k_film(const int* __restrict__ e32,
                                              float* __restrict__ out) {
    int gw = (blockIdx.x * 256 + threadIdx.x) >> 5;
    int lane = threadIdx.x & 31;
    long long base = (long long)gw * 32;

    int stride = (e32[262143] == 0 && e32[262141] == 0) ? 2 : 1;

    // per-lane own edge: index + precomputed mean
    int myi = e32[(size_t)(base + lane) * stride];
    {
    }
    int mv1 = myi >> 8;
    int mv2 = ((myi >> 16) << 8) | (myi & 255);
    float m_my = (d_sumA[mv1] + d_sumB[mv2]) * 0.0078125f;   // /128

    int gb = (int)(base >> 14);          // batch slot (32 | 16384)
    int half = lane >> 4;                // 0: even edge, 1: odd edge
    int ch = (lane & 15) * 8;            // channel base (8 channels per lane)

    float4 gv0 = *(const float4*)(d_gamma + gb * 128 + ch);
    float4 gv1 = *(const float4*)(d_gamma + gb * 128 + ch + 4);
    float4 bv0 = *(const float4*)(d_beta  + gb * 128 + ch);
    float4 bv1 = *(const float4*)(d_beta  + gb * 128 + ch + 4);

    int prev = -1;
    float4 a0 = make_float4(0.f, 0.f, 0.f, 0.f);
    float4 a1 = a0;

#pragma unroll 4
    for (int e = 0; e < 32; e += 2) {
        int i0 = __shfl_sync(0xffffffffu, myi, e);
        int i1 = __shfl_sync(0xffffffffu, myi, e + 1);
        float mn0 = __shfl_sync(0xffffffffu, m_my, e);
        float mn1 = __shfl_sync(0xffffffffu, m_my, e + 1);
        int idx = half ? i1 : i0;
        float mean = half ? mn1 : mn0;

        int v1 = idx >> 8;
        int v2 = ((idx >> 16) << 8) | (idx & 255);
        if (v1 != prev) {                // predicated per-lane reload (rare)
            const float* pa = d_AB + (size_t)v1 * 256 + ch;
            a0 = *(const float4*)pa;
            a1 = *(const float4*)(pa + 4);
            prev = v1;
        }
        const float* pb = d_AB + (size_t)v2 * 256 + 128 + ch;
        float4 b0 = *(const float4*)pb;
        float4 b1 = *(const float4*)(pb + 4);

        float4 x0, x1;
        x0.x = a0.x + b0.x; x0.y = a0.y + b0.y; x0.z = a0.z + b0.z; x0.w = a0.w + b0.w;
        x1.x = a1.x + b1.x; x1.y = a1.y + b1.y; x1.z = a1.z + b1.z; x1.w = a1.w + b1.w;

        float s2 = x0.x * x0.x;
        s2 = fmaf(x0.y, x0.y, s2); s2 = fmaf(x0.z, x0.z, s2); s2 = fmaf(x0.w, x0.w, s2);
        s2 = fmaf(x1.x, x1.x, s2); s2 = fmaf(x1.y, x1.y, s2);
        s2 = fmaf(x1.z, x1.z, s2); s2 = fmaf(x1.w, x1.w, s2);
#pragma unroll
        for (int o = 8; o; o >>= 1) s2 += __shfl_xor_sync(0xffffffffu, s2, o);

        float var = fmaf(s2, 0.0078125f, -mean * mean);
        float rs = rsqrtf(var + 1e-5f);

        float4 y0, y1;
        y0.x = fmaxf(fmaf((x0.x - mean) * rs, gv0.x, bv0.x), 0.f);
        y0.y = fmaxf(fmaf((x0.y - mean) * rs, gv0.y, bv0.y), 0.f);
        y0.z = fmaxf(fmaf((x0.z - mean) * rs, gv0.z, bv0.z), 0.f);
        y0.w = fmaxf(fmaf((x0.w - mean) * rs, gv0.w, bv0.w), 0.f);
        y1.x = fmaxf(fmaf((x1.x - mean) * rs, gv1.x, bv1.x), 0.f);
        y1.y = fmaxf(fmaf((x1.y - mean) * rs, gv1.y, bv1.y), 0.f);
        y1.z = fmaxf(fmaf((x1.z - mean) * rs, gv1.z, bv1.z), 0.f);
        y1.w = fmaxf(fmaf((x1.w - mean) * rs, gv1.w, bv1.w), 0.f);

        float* dst = out + (size_t)(base + e + half) * 128 + ch;
        __stcs((float4*)dst, y0);
        __stcs((float4*)(dst + 4), y1);
    }
}

// ---------------- launch ----------------
extern "C" void kernel_launch(void* const* d_in, const int* in_sizes, int n_in,
                              void* d_out, int out_size) {
    const float* node_feats   = (const float*)d_in[0];
    const float* cond_feats   = (const float*)d_in[1];
    const int* eidx32         = (const int*)d_in[2];
    const float* v_node       = (const float*)d_in[3];
    const float* g_node       = (const float*)d_in[4];
    const float* b_node       = (const float*)d_in[5];
    const float* v_cond       = (const float*)d_in[6];
    const float* g_cond       = (const float*)d_in[7];
    const float* b_cond       = (const float*)d_in[8];
    const float* w_film       = (const float*)d_in[9];
    const float* b_film       = (const float*)d_in[10];
    float* out = (float*)d_out;

    k_scales<<<16, 256>>>(v_node, g_node);                              // 128 warps
    k_cond<<<64, 128>>>(cond_feats, v_cond, g_cond, b_cond);            // 256 warps
    k_fused<<<128, 128>>>(node_feats, v_node, b_node, w_film, b_film);  // both GEMMs
    k_film<<<1024, 256>>>(eidx32, out);                                 // 262144 edges
}

// round 13
// speedup vs baseline: 1.2730x; 1.0716x over previous
#include <cuda_runtime.h>

// ---------------- scratch (static device globals; no allocs) ----------------
__device__ float d_scale_n[128];
__device__ float d_AB[4096 * 256];      // [ (nodes@W1^T + b_film) | nodes@W2^T ]
__device__ float d_sumA[4096];          // row sums of A half (bf folded)
__device__ float d_sumB[4096];          // row sums of B half
__device__ int2  d_einfo[262144];       // per edge: (v1<<16 | v2, bitcast mean)
__device__ float d_gamma[16 * 128];
__device__ float d_beta[16 * 128];

__device__ __forceinline__ float warp_sum(float v) {
#pragma unroll
    for (int o = 16; o; o >>= 1) v += __shfl_xor_sync(0xffffffffu, v, o);
    return v;
}

// ---------------- K1: weight-norm scales for v_node ----------------
__global__ void k_scales(const float* __restrict__ v_node, const float* __restrict__ g_node) {
    int w = (blockIdx.x * blockDim.x + threadIdx.x) >> 5;
    int lane = threadIdx.x & 31;
    const float* src = v_node + w * 512;
    float s = 0.f;
#pragma unroll
    for (int k = lane; k < 512; k += 32) { float v = src[k]; s += v * v; }
    s = warp_sum(s);
    if (lane == 0) d_scale_n[w] = g_node[w] * rsqrtf(s);
}

// ---------------- K_cond: one warp per channel c; cond staged in smem --------
__global__ void __launch_bounds__(128) k_cond(const float* __restrict__ cond,
                                              const float* __restrict__ vc,
                                              const float* __restrict__ gc,
                                              const float* __restrict__ bc) {
    __shared__ float cs[16 * 512];   // 32 KB
    int tid = threadIdx.x;
    for (int i = tid; i < 16 * 512 / 4; i += 128)
        ((float4*)cs)[i] = ((const float4*)cond)[i];
    __syncthreads();

    int c = blockIdx.x * 4 + (tid >> 5);
    int lane = tid & 31;
    const float* vr = vc + (size_t)c * 512;

    float v[16];
    float q = 0.f;
#pragma unroll
    for (int i = 0; i < 16; i++) { v[i] = vr[lane + 32 * i]; q = fmaf(v[i], v[i], q); }
    q = warp_sum(q);
    float sc = gc[c] * rsqrtf(q);
    float bias = bc[c];

#pragma unroll
    for (int b = 0; b < 16; b++) {
        const float* cr = cs + b * 512;
        float s = 0.f;
#pragma unroll
        for (int i = 0; i < 16; i++) s = fmaf(cr[lane + 32 * i], v[i], s);
        s = warp_sum(s);
        if (lane == 0) {
            float r = fmaf(s, sc, bias);
            if (c < 128) d_gamma[b * 128 + c] = r + 1.f;
            else         d_beta[b * 128 + (c - 128)] = r;
        }
    }
}

// ---------------- Fused GEMM: nodes tile -> AB tile (+ bf fold + row sums) ----
// grid 128 x 128 threads. BM=32 rows per block.
__global__ void __launch_bounds__(128) k_fused(const float* __restrict__ nf,
                                               const float* __restrict__ vn,
                                               const float* __restrict__ bn,
                                               const float* __restrict__ wf,
                                               const float* __restrict__ bf) {
    __shared__ float As1[16][32];    // [k][m]
    __shared__ float Bs1[16][128];   // [k][n]
    __shared__ float Ns[128][33];    // [k2][m] transposed nodes tile, padded
    __shared__ float Bs2[16][256];   // [k][n]

    int tid = threadIdx.x;
    int mb = blockIdx.x * 32;
    int m0 = (tid >> 5) * 8;         // warp-uniform
    int n0 = (tid & 31) * 4;         // phase-1 col group

    // -------- Phase 1: N1(32x128) = relu(nf @ (vn*scale)^T + bn) --------
    int ar = tid & 31, ac = (tid >> 5) * 4;
    int br = tid >> 2, bk = (tid & 3) * 4;

    const float* Arow = nf + (size_t)(mb + ar) * 512 + ac;
    const float* B0 = vn + (size_t)(br +  0) * 512 + bk;
    const float* B1 = vn + (size_t)(br + 32) * 512 + bk;
    const float* B2 = vn + (size_t)(br + 64) * 512 + bk;
    const float* B3 = vn + (size_t)(br + 96) * 512 + bk;

    float4 aR = *(const float4*)Arow;
    float4 bR0 = *(const float4*)B0, bR1 = *(const float4*)B1;
    float4 bR2 = *(const float4*)B2, bR3 = *(const float4*)B3;

    float acc[8][4];
#pragma unroll
    for (int i = 0; i < 8; i++)
#pragma unroll
        for (int j = 0; j < 4; j++) acc[i][j] = 0.f;

#pragma unroll 1
    for (int c = 0; c < 32; c++) {
        __syncthreads();
        As1[ac + 0][ar] = aR.x; As1[ac + 1][ar] = aR.y;
        As1[ac + 2][ar] = aR.z; As1[ac + 3][ar] = aR.w;
        Bs1[bk + 0][br +  0] = bR0.x; Bs1[bk + 1][br +  0] = bR0.y; Bs1[bk + 2][br +  0] = bR0.z; Bs1[bk + 3][br +  0] = bR0.w;
        Bs1[bk + 0][br + 32] = bR1.x; Bs1[bk + 1][br + 32] = bR1.y; Bs1[bk + 2][br + 32] = bR1.z; Bs1[bk + 3][br + 32] = bR1.w;
        Bs1[bk + 0][br + 64] = bR2.x; Bs1[bk + 1][br + 64] = bR2.y; Bs1[bk + 2][br + 64] = bR2.z; Bs1[bk + 3][br + 64] = bR2.w;
        Bs1[bk + 0][br + 96] = bR3.x; Bs1[bk + 1][br + 96] = bR3.y; Bs1[bk + 2][br + 96] = bR3.z; Bs1[bk + 3][br + 96] = bR3.w;
        __syncthreads();
        if (c < 31) {
            int k0 = (c + 1) * 16;
            aR  = *(const float4*)(Arow + k0);
            bR0 = *(const float4*)(B0 + k0);
            bR1 = *(const float4*)(B1 + k0);
            bR2 = *(const float4*)(B2 + k0);
            bR3 = *(const float4*)(B3 + k0);
        }
#pragma unroll
        for (int k = 0; k < 16; k++) {
            float4 aLo = *(const float4*)&As1[k][m0];        // broadcast within warp
            float4 aHi = *(const float4*)&As1[k][m0 + 4];
            float4 b = *(const float4*)&Bs1[k][n0];
            float a[8] = {aLo.x, aLo.y, aLo.z, aLo.w, aHi.x, aHi.y, aHi.z, aHi.w};
#pragma unroll
            for (int i = 0; i < 8; i++) {
                acc[i][0] = fmaf(a[i], b.x, acc[i][0]);
                acc[i][1] = fmaf(a[i], b.y, acc[i][1]);
                acc[i][2] = fmaf(a[i], b.z, acc[i][2]);
                acc[i][3] = fmaf(a[i], b.w, acc[i][3]);
            }
        }
    }

    // epilogue: relu(acc*scale+bias) -> Ns[n][m]
    {
        float4 sc4 = *(const float4*)&d_scale_n[n0];
        float4 bb4 = *(const float4*)&bn[n0];
        __syncthreads();
#pragma unroll
        for (int i = 0; i < 8; i++) {
            Ns[n0 + 0][m0 + i] = fmaxf(fmaf(acc[i][0], sc4.x, bb4.x), 0.f);
            Ns[n0 + 1][m0 + i] = fmaxf(fmaf(acc[i][1], sc4.y, bb4.y), 0.f);
            Ns[n0 + 2][m0 + i] = fmaxf(fmaf(acc[i][2], sc4.z, bb4.z), 0.f);
            Ns[n0 + 3][m0 + i] = fmaxf(fmaf(acc[i][3], sc4.w, bb4.w), 0.f);
        }
    }
    __syncthreads();

    // -------- Phase 2: AB(32x256) = Ns^T @ Wt^T, K=128 --------
    int lane = tid & 31;
    int n2 = lane * 8;                       // output col group (8 cols)
    int br2 = tid >> 2, bk2 = (tid & 3) * 4; // B loader
    int roff[8];
#pragma unroll
    for (int j = 0; j < 8; j++) {
        int n = br2 + 32 * j;
        roff[j] = (j < 4) ? n * 256 + bk2 : (n - 128) * 256 + 128 + bk2;
    }

    float4 w0 = *(const float4*)(wf + roff[0]);
    float4 w1 = *(const float4*)(wf + roff[1]);
    float4 w2 = *(const float4*)(wf + roff[2]);
    float4 w3 = *(const float4*)(wf + roff[3]);
    float4 w4 = *(const float4*)(wf + roff[4]);
    float4 w5 = *(const float4*)(wf + roff[5]);
    float4 w6 = *(const float4*)(wf + roff[6]);
    float4 w7 = *(const float4*)(wf + roff[7]);

    float acc2[8][8];
#pragma unroll
    for (int i = 0; i < 8; i++)
#pragma unroll
        for (int j = 0; j < 8; j++) acc2[i][j] = 0.f;

#pragma unroll 1
    for (int c = 0; c < 8; c++) {
        __syncthreads();
        Bs2[bk2 + 0][br2 +   0] = w0.x; Bs2[bk2 + 1][br2 +   0] = w0.y; Bs2[bk2 + 2][br2 +   0] = w0.z; Bs2[bk2 + 3][br2 +   0] = w0.w;
        Bs2[bk2 + 0][br2 +  32] = w1.x; Bs2[bk2 + 1][br2 +  32] = w1.y; Bs2[bk2 + 2][br2 +  32] = w1.z; Bs2[bk2 + 3][br2 +  32] = w1.w;
        Bs2[bk2 + 0][br2 +  64] = w2.x; Bs2[bk2 + 1][br2 +  64] = w2.y; Bs2[bk2 + 2][br2 +  64] = w2.z; Bs2[bk2 + 3][br2 +  64] = w2.w;
        Bs2[bk2 + 0][br2 +  96] = w3.x; Bs2[bk2 + 1][br2 +  96] = w3.y; Bs2[bk2 + 2][br2 +  96] = w3.z; Bs2[bk2 + 3][br2 +  96] = w3.w;
        Bs2[bk2 + 0][br2 + 128] = w4.x; Bs2[bk2 + 1][br2 + 128] = w4.y; Bs2[bk2 + 2][br2 + 128] = w4.z; Bs2[bk2 + 3][br2 + 128] = w4.w;
        Bs2[bk2 + 0][br2 + 160] = w5.x; Bs2[bk2 + 1][br2 + 160] = w5.y; Bs2[bk2 + 2][br2 + 160] = w5.z; Bs2[bk2 + 3][br2 + 160] = w5.w;
        Bs2[bk2 + 0][br2 + 192] = w6.x; Bs2[bk2 + 1][br2 + 192] = w6.y; Bs2[bk2 + 2][br2 + 192] = w6.z; Bs2[bk2 + 3][br2 + 192] = w6.w;
        Bs2[bk2 + 0][br2 + 224] = w7.x; Bs2[bk2 + 1][br2 + 224] = w7.y; Bs2[bk2 + 2][br2 + 224] = w7.z; Bs2[bk2 + 3][br2 + 224] = w7.w;
        __syncthreads();
        if (c < 7) {
            int k0 = (c + 1) * 16;
            w0 = *(const float4*)(wf + roff[0] + k0);
            w1 = *(const float4*)(wf + roff[1] + k0);
            w2 = *(const float4*)(wf + roff[2] + k0);
            w3 = *(const float4*)(wf + roff[3] + k0);
            w4 = *(const float4*)(wf + roff[4] + k0);
            w5 = *(const float4*)(wf + roff[5] + k0);
            w6 = *(const float4*)(wf + roff[6] + k0);
            w7 = *(const float4*)(wf + roff[7] + k0);
        }
        int kbase = c * 16;
#pragma unroll
        for (int k = 0; k < 16; k++) {
            const float* nrow = &Ns[kbase + k][m0];   // broadcast within warp
            float4 bLo = *(const float4*)&Bs2[k][n2];
            float4 bHi = *(const float4*)&Bs2[k][n2 + 4];
            float b[8] = {bLo.x, bLo.y, bLo.z, bLo.w, bHi.x, bHi.y, bHi.z, bHi.w};
#pragma unroll
            for (int i = 0; i < 8; i++) {
                float a = nrow[i];
#pragma unroll
                for (int j = 0; j < 8; j++) acc2[i][j] = fmaf(a, b[j], acc2[i][j]);
            }
        }
    }

    // -------- Epilogue: fold b_film into A half, write AB, emit row sums --------
    // lanes 0..15 hold cols [0,128) (A half); lanes 16..31 hold cols [128,256) (B half)
    if (lane < 16) {
        float4 f0 = *(const float4*)(bf + n2);
        float4 f1 = *(const float4*)(bf + n2 + 4);
#pragma unroll
        for (int i = 0; i < 8; i++) {
            acc2[i][0] += f0.x; acc2[i][1] += f0.y; acc2[i][2] += f0.z; acc2[i][3] += f0.w;
            acc2[i][4] += f1.x; acc2[i][5] += f1.y; acc2[i][6] += f1.z; acc2[i][7] += f1.w;
        }
    }

#pragma unroll
    for (int i = 0; i < 8; i++) {
        float4 o0, o1;
        o0.x = acc2[i][0]; o0.y = acc2[i][1]; o0.z = acc2[i][2]; o0.w = acc2[i][3];
        o1.x = acc2[i][4]; o1.y = acc2[i][5]; o1.z = acc2[i][6]; o1.w = acc2[i][7];
        float* dst = &d_AB[(size_t)(mb + m0 + i) * 256 + n2];
        *(float4*)dst = o0;
        *(float4*)(dst + 4) = o1;

        // row sum within each 16-lane half (xor <= 8 keeps halves separate)
        float rsum = ((acc2[i][0] + acc2[i][1]) + (acc2[i][2] + acc2[i][3]))
                   + ((acc2[i][4] + acc2[i][5]) + (acc2[i][6] + acc2[i][7]));
#pragma unroll
        for (int o = 8; o; o >>= 1) rsum += __shfl_xor_sync(0xffffffffu, rsum, o);
        if (lane == 0)  d_sumA[mb + m0 + i] = rsum;
        if (lane == 16) d_sumB[mb + m0 + i] = rsum;
    }
}

// ---------------- K_mean: per-edge (v1|v2, mean) table ----------------
// 65536 threads x 4 edges. Moves idx decode + mean lookup + dtype probe out of
// the hot k_film loop; k_film then does one uniform LDG.64 per edge.
// dtype probe: int64 (LE) buffer has zero odd words; int32 has nonzero tail words.
__global__ void __launch_bounds__(256) k_mean(const int* __restrict__ e32) {
    int t = blockIdx.x * 256 + threadIdx.x;
    int stride = (e32[262143] == 0 && e32[262141] == 0) ? 2 : 1;
#pragma unroll
    for (int j = 0; j < 4; j++) {
        int e = t * 4 + j;
        int idx = e32[(size_t)e * stride];
        int v1 = idx >> 8;                              // b*256 + i
        int v2 = ((idx >> 16) << 8) | (idx & 255);      // b*256 + j
        float m = (d_sumA[v1] + d_sumB[v2]) * 0.0078125f;
        d_einfo[e] = make_int2((v1 << 16) | v2, __float_as_int(m));
    }
}

// ---------------- K4: per-edge gather + layernorm + FiLM + relu ----------------
// Full warp per edge (contiguous 512B accesses = 4 wavefronts/instr). Mean is
// precomputed; per edge: 1 broadcast LDG.64 + 1 LDG.128 + 5 shfl + 1 STG.128.
// A-row cached in registers keyed on v1 (sorted edges, mean run-length ~64).
__global__ void __launch_bounds__(256) k_film(float* __restrict__ out) {
    int gw = (blockIdx.x * 256 + threadIdx.x) >> 5;
    int lane = threadIdx.x & 31;
    long long base = (long long)gw * 32;

    int gb = (int)(base >> 14);          // batch slot (32 | 16384)
    float4 gv = *(const float4*)(d_gamma + gb * 128 + lane * 4);
    float4 bv = *(const float4*)(d_beta  + gb * 128 + lane * 4);

    int prev = -1;
    float4 xa = make_float4(0.f, 0.f, 0.f, 0.f);
    const int2* einfo = d_einfo + base;

#pragma unroll 4
    for (int e = 0; e < 32; e++) {
        int2 info = einfo[e];                           // uniform address: broadcast
        int v1 = info.x >> 16;
        int v2 = info.x & 0xFFFF;
        float mean = __int_as_float(info.y);

        if (v1 != prev) {                               // warp-uniform branch
            xa = *(const float4*)(d_AB + (size_t)v1 * 256 + lane * 4);
            prev = v1;
        }
        float4 xb = *(const float4*)(d_AB + (size_t)v2 * 256 + 128 + lane * 4);
        float4 x;
        x.x = xa.x + xb.x;
        x.y = xa.y + xb.y;
        x.z = xa.z + xb.z;
        x.w = xa.w + xb.w;

        float s2 = x.x * x.x;
        s2 = fmaf(x.y, x.y, s2);
        s2 = fmaf(x.z, x.z, s2);
        s2 = fmaf(x.w, x.w, s2);
#pragma unroll
        for (int o = 16; o; o >>= 1) s2 += __shfl_xor_sync(0xffffffffu, s2, o);

        float var = fmaf(s2, 0.0078125f, -mean * mean);
        float rs = rsqrtf(var + 1e-5f);

        float4 y;
        y.x = fmaxf(fmaf((x.x - mean) * rs, gv.x, bv.x), 0.f);
        y.y = fmaxf(fmaf((x.y - mean) * rs, gv.y, bv.y), 0.f);
        y.z = fmaxf(fmaf((x.z - mean) * rs, gv.z, bv.z), 0.f);
        y.w = fmaxf(fmaf((x.w - mean) * rs, gv.w, bv.w), 0.f);
        __stcs((float4*)(out + (size_t)(base + e) * 128 + lane * 4), y);
    }
}

// ---------------- launch ----------------
extern "C" void kernel_launch(void* const* d_in, const int* in_sizes, int n_in,
                              void* d_out, int out_size) {
    const float* node_feats   = (const float*)d_in[0];
    const float* cond_feats   = (const float*)d_in[1];
    const int* eidx32         = (const int*)d_in[2];
    const float* v_node       = (const float*)d_in[3];
    const float* g_node       = (const float*)d_in[4];
    const float* b_node       = (const float*)d_in[5];
    const float* v_cond       = (const float*)d_in[6];
    const float* g_cond       = (const float*)d_in[7];
    const float* b_cond       = (const float*)d_in[8];
    const float* w_film       = (const float*)d_in[9];
    const float* b_film       = (const float*)d_in[10];
    float* out = (float*)d_out;

    k_scales<<<16, 256>>>(v_node, g_node);                              // 128 warps
    k_cond<<<64, 128>>>(cond_feats, v_cond, g_cond, b_cond);            // 256 warps
    k_fused<<<128, 128>>>(node_feats, v_node, b_node, w_film, b_film);  // both GEMMs
    k_mean<<<256, 256>>>(eidx32);                                       // edge table
    k_film<<<1024, 256>>>(out);                                         // 262144 edges
}

// round 15
// speedup vs baseline: 1.2735x; 1.0004x over previous
#include <cuda_runtime.h>

// ---------------- scratch (static device globals; no allocs) ----------------
__device__ float d_scale_n[128];
__device__ float d_AB[4096 * 256];      // [ (nodes@W1^T + b_film) | nodes@W2^T ]
__device__ float d_sumA[4096];          // row sums of A half (bf folded)
__device__ float d_sumB[4096];          // row sums of B half
__device__ int2  d_einfo[262144];       // per edge: (v1<<16 | v2, bitcast mean)
__device__ float d_gamma[16 * 128];
__device__ float d_beta[16 * 128];

__device__ __forceinline__ float warp_sum(float v) {
#pragma unroll
    for (int o = 16; o; o >>= 1) v += __shfl_xor_sync(0xffffffffu, v, o);
    return v;
}

// ---------------- K1: weight-norm scales for v_node ----------------
__global__ void k_scales(const float* __restrict__ v_node, const float* __restrict__ g_node) {
    int w = (blockIdx.x * blockDim.x + threadIdx.x) >> 5;
    int lane = threadIdx.x & 31;
    const float* src = v_node + w * 512;
    float s = 0.f;
#pragma unroll
    for (int k = lane; k < 512; k += 32) { float v = src[k]; s += v * v; }
    s = warp_sum(s);
    if (lane == 0) d_scale_n[w] = g_node[w] * rsqrtf(s);
}

// ---------------- K_cond: one warp per channel c; cond staged in smem --------
__global__ void __launch_bounds__(128) k_cond(const float* __restrict__ cond,
                                              const float* __restrict__ vc,
                                              const float* __restrict__ gc,
                                              const float* __restrict__ bc) {
    __shared__ float cs[16 * 512];   // 32 KB
    int tid = threadIdx.x;
    for (int i = tid; i < 16 * 512 / 4; i += 128)
        ((float4*)cs)[i] = ((const float4*)cond)[i];
    __syncthreads();

    int c = blockIdx.x * 4 + (tid >> 5);
    int lane = tid & 31;
    const float* vr = vc + (size_t)c * 512;

    float v[16];
    float q = 0.f;
#pragma unroll
    for (int i = 0; i < 16; i++) { v[i] = vr[lane + 32 * i]; q = fmaf(v[i], v[i], q); }
    q = warp_sum(q);
    float sc = gc[c] * rsqrtf(q);
    float bias = bc[c];

#pragma unroll
    for (int b = 0; b < 16; b++) {
        const float* cr = cs + b * 512;
        float s = 0.f;
#pragma unroll
        for (int i = 0; i < 16; i++) s = fmaf(cr[lane + 32 * i], v[i], s);
        s = warp_sum(s);
        if (lane == 0) {
            float r = fmaf(s, sc, bias);
            if (c < 128) d_gamma[b * 128 + c] = r + 1.f;
            else         d_beta[b * 128 + (c - 128)] = r;
        }
    }
}

// ---------------- Fused GEMM: nodes tile -> AB tile (+ bf fold + row sums) ----
// grid 128 x 128 threads. BM=32 rows per block.
__global__ void __launch_bounds__(128) k_fused(const float* __restrict__ nf,
                                               const float* __restrict__ vn,
                                               const float* __restrict__ bn,
                                               const float* __restrict__ wf,
                                               const float* __restrict__ bf) {
    __shared__ float As1[16][32];    // [k][m]
    __shared__ float Bs1[16][128];   // [k][n]
    __shared__ float Ns[128][33];    // [k2][m] transposed nodes tile, padded
    __shared__ float Bs2[16][256];   // [k][n]

    int tid = threadIdx.x;
    int mb = blockIdx.x * 32;
    int m0 = (tid >> 5) * 8;         // warp-uniform
    int n0 = (tid & 31) * 4;         // phase-1 col group

    // -------- Phase 1: N1(32x128) = relu(nf @ (vn*scale)^T + bn) --------
    int ar = tid & 31, ac = (tid >> 5) * 4;
    int br = tid >> 2, bk = (tid & 3) * 4;

    const float* Arow = nf + (size_t)(mb + ar) * 512 + ac;
    const float* B0 = vn + (size_t)(br +  0) * 512 + bk;
    const float* B1 = vn + (size_t)(br + 32) * 512 + bk;
    const float* B2 = vn + (size_t)(br + 64) * 512 + bk;
    const float* B3 = vn + (size_t)(br + 96) * 512 + bk;

    float4 aR = *(const float4*)Arow;
    float4 bR0 = *(const float4*)B0, bR1 = *(const float4*)B1;
    float4 bR2 = *(const float4*)B2, bR3 = *(const float4*)B3;

    float acc[8][4];
#pragma unroll
    for (int i = 0; i < 8; i++)
#pragma unroll
        for (int j = 0; j < 4; j++) acc[i][j] = 0.f;

#pragma unroll 1
    for (int c = 0; c < 32; c++) {
        __syncthreads();
        As1[ac + 0][ar] = aR.x; As1[ac + 1][ar] = aR.y;
        As1[ac + 2][ar] = aR.z; As1[ac + 3][ar] = aR.w;
        Bs1[bk + 0][br +  0] = bR0.x; Bs1[bk + 1][br +  0] = bR0.y; Bs1[bk + 2][br +  0] = bR0.z; Bs1[bk + 3][br +  0] = bR0.w;
        Bs1[bk + 0][br + 32] = bR1.x; Bs1[bk + 1][br + 32] = bR1.y; Bs1[bk + 2][br + 32] = bR1.z; Bs1[bk + 3][br + 32] = bR1.w;
        Bs1[bk + 0][br + 64] = bR2.x; Bs1[bk + 1][br + 64] = bR2.y; Bs1[bk + 2][br + 64] = bR2.z; Bs1[bk + 3][br + 64] = bR2.w;
        Bs1[bk + 0][br + 96] = bR3.x; Bs1[bk + 1][br + 96] = bR3.y; Bs1[bk + 2][br + 96] = bR3.z; Bs1[bk + 3][br + 96] = bR3.w;
        __syncthreads();
        if (c < 31) {
            int k0 = (c + 1) * 16;
            aR  = *(const float4*)(Arow + k0);
            bR0 = *(const float4*)(B0 + k0);
            bR1 = *(const float4*)(B1 + k0);
            bR2 = *(const float4*)(B2 + k0);
            bR3 = *(const float4*)(B3 + k0);
        }
#pragma unroll
        for (int k = 0; k < 16; k++) {
            float4 aLo = *(const float4*)&As1[k][m0];        // broadcast within warp
            float4 aHi = *(const float4*)&As1[k][m0 + 4];
            float4 b = *(const float4*)&Bs1[k][n0];
            float a[8] = {aLo.x, aLo.y, aLo.z, aLo.w, aHi.x, aHi.y, aHi.z, aHi.w};
#pragma unroll
            for (int i = 0; i < 8; i++) {
                acc[i][0] = fmaf(a[i], b.x, acc[i][0]);
                acc[i][1] = fmaf(a[i], b.y, acc[i][1]);
                acc[i][2] = fmaf(a[i], b.z, acc[i][2]);
                acc[i][3] = fmaf(a[i], b.w, acc[i][3]);
            }
        }
    }

    // epilogue: relu(acc*scale+bias) -> Ns[n][m]
    {
        float4 sc4 = *(const float4*)&d_scale_n[n0];
        float4 bb4 = *(const float4*)&bn[n0];
        __syncthreads();
#pragma unroll
        for (int i = 0; i < 8; i++) {
            Ns[n0 + 0][m0 + i] = fmaxf(fmaf(acc[i][0], sc4.x, bb4.x), 0.f);
            Ns[n0 + 1][m0 + i] = fmaxf(fmaf(acc[i][1], sc4.y, bb4.y), 0.f);
            Ns[n0 + 2][m0 + i] = fmaxf(fmaf(acc[i][2], sc4.z, bb4.z), 0.f);
            Ns[n0 + 3][m0 + i] = fmaxf(fmaf(acc[i][3], sc4.w, bb4.w), 0.f);
        }
    }
    __syncthreads();

    // -------- Phase 2: AB(32x256) = Ns^T @ Wt^T, K=128 --------
    int lane = tid & 31;
    int n2 = lane * 8;                       // output col group (8 cols)
    int br2 = tid >> 2, bk2 = (tid & 3) * 4; // B loader
    int roff[8];
#pragma unroll
    for (int j = 0; j < 8; j++) {
        int n = br2 + 32 * j;
        roff[j] = (j < 4) ? n * 256 + bk2 : (n - 128) * 256 + 128 + bk2;
    }

    float4 w0 = *(const float4*)(wf + roff[0]);
    float4 w1 = *(const float4*)(wf + roff[1]);
    float4 w2 = *(const float4*)(wf + roff[2]);
    float4 w3 = *(const float4*)(wf + roff[3]);
    float4 w4 = *(const float4*)(wf + roff[4]);
    float4 w5 = *(const float4*)(wf + roff[5]);
    float4 w6 = *(const float4*)(wf + roff[6]);
    float4 w7 = *(const float4*)(wf + roff[7]);

    float acc2[8][8];
#pragma unroll
    for (int i = 0; i < 8; i++)
#pragma unroll
        for (int j = 0; j < 8; j++) acc2[i][j] = 0.f;

#pragma unroll 1
    for (int c = 0; c < 8; c++) {
        __syncthreads();
        Bs2[bk2 + 0][br2 +   0] = w0.x; Bs2[bk2 + 1][br2 +   0] = w0.y; Bs2[bk2 + 2][br2 +   0] = w0.z; Bs2[bk2 + 3][br2 +   0] = w0.w;
        Bs2[bk2 + 0][br2 +  32] = w1.x; Bs2[bk2 + 1][br2 +  32] = w1.y; Bs2[bk2 + 2][br2 +  32] = w1.z; Bs2[bk2 + 3][br2 +  32] = w1.w;
        Bs2[bk2 + 0][br2 +  64] = w2.x; Bs2[bk2 + 1][br2 +  64] = w2.y; Bs2[bk2 + 2][br2 +  64] = w2.z; Bs2[bk2 + 3][br2 +  64] = w2.w;
        Bs2[bk2 + 0][br2 +  96] = w3.x; Bs2[bk2 + 1][br2 +  96] = w3.y; Bs2[bk2 + 2][br2 +  96] = w3.z; Bs2[bk2 + 3][br2 +  96] = w3.w;
        Bs2[bk2 + 0][br2 + 128] = w4.x; Bs2[bk2 + 1][br2 + 128] = w4.y; Bs2[bk2 + 2][br2 + 128] = w4.z; Bs2[bk2 + 3][br2 + 128] = w4.w;
        Bs2[bk2 + 0][br2 + 160] = w5.x; Bs2[bk2 + 1][br2 + 160] = w5.y; Bs2[bk2 + 2][br2 + 160] = w5.z; Bs2[bk2 + 3][br2 + 160] = w5.w;
        Bs2[bk2 + 0][br2 + 192] = w6.x; Bs2[bk2 + 1][br2 + 192] = w6.y; Bs2[bk2 + 2][br2 + 192] = w6.z; Bs2[bk2 + 3][br2 + 192] = w6.w;
        Bs2[bk2 + 0][br2 + 224] = w7.x; Bs2[bk2 + 1][br2 + 224] = w7.y; Bs2[bk2 + 2][br2 + 224] = w7.z; Bs2[bk2 + 3][br2 + 224] = w7.w;
        __syncthreads();
        if (c < 7) {
            int k0 = (c + 1) * 16;
            w0 = *(const float4*)(wf + roff[0] + k0);
            w1 = *(const float4*)(wf + roff[1] + k0);
            w2 = *(const float4*)(wf + roff[2] + k0);
            w3 = *(const float4*)(wf + roff[3] + k0);
            w4 = *(const float4*)(wf + roff[4] + k0);
            w5 = *(const float4*)(wf + roff[5] + k0);
            w6 = *(const float4*)(wf + roff[6] + k0);
            w7 = *(const float4*)(wf + roff[7] + k0);
        }
        int kbase = c * 16;
#pragma unroll
        for (int k = 0; k < 16; k++) {
            const float* nrow = &Ns[kbase + k][m0];   // broadcast within warp
            float4 bLo = *(const float4*)&Bs2[k][n2];
            float4 bHi = *(const float4*)&Bs2[k][n2 + 4];
            float b[8] = {bLo.x, bLo.y, bLo.z, bLo.w, bHi.x, bHi.y, bHi.z, bHi.w};
#pragma unroll
            for (int i = 0; i < 8; i++) {
                float a = nrow[i];
#pragma unroll
                for (int j = 0; j < 8; j++) acc2[i][j] = fmaf(a, b[j], acc2[i][j]);
            }
        }
    }

    // -------- Epilogue: fold b_film into A half, write AB, emit row sums --------
    // lanes 0..15 hold cols [0,128) (A half); lanes 16..31 hold cols [128,256) (B half)
    if (lane < 16) {
        float4 f0 = *(const float4*)(bf + n2);
        float4 f1 = *(const float4*)(bf + n2 + 4);
#pragma unroll
        for (int i = 0; i < 8; i++) {
            acc2[i][0] += f0.x; acc2[i][1] += f0.y; acc2[i][2] += f0.z; acc2[i][3] += f0.w;
            acc2[i][4] += f1.x; acc2[i][5] += f1.y; acc2[i][6] += f1.z; acc2[i][7] += f1.w;
        }
    }

#pragma unroll
    for (int i = 0; i < 8; i++) {
        float4 o0, o1;
        o0.x = acc2[i][0]; o0.y = acc2[i][1]; o0.z = acc2[i][2]; o0.w = acc2[i][3];
        o1.x = acc2[i][4]; o1.y = acc2[i][5]; o1.z = acc2[i][6]; o1.w = acc2[i][7];
        float* dst = &d_AB[(size_t)(mb + m0 + i) * 256 + n2];
        *(float4*)dst = o0;
        *(float4*)(dst + 4) = o1;

        // row sum within each 16-lane half (xor <= 8 keeps halves separate)
        float rsum = ((acc2[i][0] + acc2[i][1]) + (acc2[i][2] + acc2[i][3]))
                   + ((acc2[i][4] + acc2[i][5]) + (acc2[i][6] + acc2[i][7]));
#pragma unroll
        for (int o = 8; o; o >>= 1) rsum += __shfl_xor_sync(0xffffffffu, rsum, o);
        if (lane == 0)  d_sumA[mb + m0 + i] = rsum;
        if (lane == 16) d_sumB[mb + m0 + i] = rsum;
    }
}

// ---------------- K_mean: per-edge (v1|v2, mean) table ----------------
// 1 edge per thread, grid 1024 x 256 = 262144 threads: enough resident warps to
// fully overlap the e32-load -> sum-gather -> store dependency chain (R13 ran
// grid=256 with a 4-edge loop and sat at issue=7% pure exposed latency).
// dtype probe: int64 (LE) buffer has zero odd words; int32 has nonzero tail words.
__global__ void __launch_bounds__(256) k_mean(const int* __restrict__ e32) {
    int e = blockIdx.x * 256 + threadIdx.x;
    int stride = (e32[262143] == 0 && e32[262141] == 0) ? 2 : 1;
    int idx = e32[(size_t)e * stride];
    int v1 = idx >> 8;                              // b*256 + i
    int v2 = ((idx >> 16) << 8) | (idx & 255);      // b*256 + j
    float m = (d_sumA[v1] + d_sumB[v2]) * 0.0078125f;
    d_einfo[e] = make_int2((v1 << 16) | v2, __float_as_int(m));
}

// ---------------- K4: per-edge gather + layernorm + FiLM + relu ----------------
// Full warp per edge (contiguous 512B accesses = 4 wavefronts/instr). Mean is
// precomputed; variance uses the 5-level SHFL butterfly (redux.sync.add.f32
// does NOT exist on sm_103 — integer only; verified by ptxas in R14).
// A-row cached in registers keyed on v1 (sorted edges, mean run-length ~64).
__global__ void __launch_bounds__(256) k_film(float* __restrict__ out) {
    int gw = (blockIdx.x * 256 + threadIdx.x) >> 5;
    int lane = threadIdx.x & 31;
    long long base = (long long)gw * 32;

    int gb = (int)(base >> 14);          // batch slot (32 | 16384)
    float4 gv = *(const float4*)(d_gamma + gb * 128 + lane * 4);
    float4 bv = *(const float4*)(d_beta  + gb * 128 + lane * 4);

    int prev = -1;
    float4 xa = make_float4(0.f, 0.f, 0.f, 0.f);
    const int2* einfo = d_einfo + base;

#pragma unroll 4
    for (int e = 0; e < 32; e++) {
        int2 info = einfo[e];                           // uniform address: broadcast
        int v1 = info.x >> 16;
        int v2 = info.x & 0xFFFF;
        float mean = __int_as_float(info.y);

        if (v1 != prev) {                               // warp-uniform branch
            xa = *(const float4*)(d_AB + (size_t)v1 * 256 + lane * 4);
            prev = v1;
        }
        float4 xb = *(const float4*)(d_AB + (size_t)v2 * 256 + 128 + lane * 4);
        float4 x;
        x.x = xa.x + xb.x;
        x.y = xa.y + xb.y;
        x.z = xa.z + xb.z;
        x.w = xa.w + xb.w;

        float s2 = x.x * x.x;
        s2 = fmaf(x.y, x.y, s2);
        s2 = fmaf(x.z, x.z, s2);
        s2 = fmaf(x.w, x.w, s2);
#pragma unroll
        for (int o = 16; o; o >>= 1) s2 += __shfl_xor_sync(0xffffffffu, s2, o);

        float var = fmaf(s2, 0.0078125f, -mean * mean);
        float rs = rsqrtf(var + 1e-5f);

        float4 y;
        y.x = fmaxf(fmaf((x.x - mean) * rs, gv.x, bv.x), 0.f);
        y.y = fmaxf(fmaf((x.y - mean) * rs, gv.y, bv.y), 0.f);
        y.z = fmaxf(fmaf((x.z - mean) * rs, gv.z, bv.z), 0.f);
        y.w = fmaxf(fmaf((x.w - mean) * rs, gv.w, bv.w), 0.f);
        __stcs((float4*)(out + (size_t)(base + e) * 128 + lane * 4), y);
    }
}

// ---------------- launch ----------------
extern "C" void kernel_launch(void* const* d_in, const int* in_sizes, int n_in,
                              void* d_out, int out_size) {
    const float* node_feats   = (const float*)d_in[0];
    const float* cond_feats   = (const float*)d_in[1];
    const int* eidx32         = (const int*)d_in[2];
    const float* v_node       = (const float*)d_in[3];
    const float* g_node       = (const float*)d_in[4];
    const float* b_node       = (const float*)d_in[5];
    const float* v_cond       = (const float*)d_in[6];
    const float* g_cond       = (const float*)d_in[7];
    const float* b_cond       = (const float*)d_in[8];
    const float* w_film       = (const float*)d_in[9];
    const float* b_film       = (const float*)d_in[10];
    float* out = (float*)d_out;

    k_scales<<<16, 256>>>(v_node, g_node);                              // 128 warps
    k_cond<<<64, 128>>>(cond_feats, v_cond, g_cond, b_cond);            // 256 warps
    k_fused<<<128, 128>>>(node_feats, v_node, b_node, w_film, b_film);  // both GEMMs
    k_mean<<<1024, 256>>>(eidx32);                                      // edge table
    k_film<<<1024, 256>>>(out);                                         // 262144 edges
}

// round 16
// speedup vs baseline: 1.3017x; 1.0221x over previous
#include <cuda_runtime.h>

// ---------------- scratch (static device globals; no allocs) ----------------
__device__ float d_scale_n[128];
__device__ float d_AB[4096 * 256];      // [ (nodes@W1^T + b_film) | nodes@W2^T ]
__device__ float d_sumA[4096];          // row sums of A half (bf folded)
__device__ float d_sumB[4096];          // row sums of B half
__device__ float d_gamma[16 * 128];
__device__ float d_beta[16 * 128];

typedef unsigned long long ull;

__device__ __forceinline__ float warp_sum(float v) {
#pragma unroll
    for (int o = 16; o; o >>= 1) v += __shfl_xor_sync(0xffffffffu, v, o);
    return v;
}

// Packed fp32x2 FMA (sm_100+/sm_103a): full fp32 precision, 2 lane-FMAs/instr.
__device__ __forceinline__ ull fma2(ull a, ull b, ull c) {
    ull d;
    asm("fma.rn.f32x2 %0, %1, %2, %3;" : "=l"(d) : "l"(a), "l"(b), "l"(c));
    return d;
}
__device__ __forceinline__ ull pack2(float x, float y) {
    ull d;
    asm("mov.b64 %0, {%1, %2};" : "=l"(d) : "f"(x), "f"(y));
    return d;
}
__device__ __forceinline__ void unpack2(float& x, float& y, ull d) {
    asm("mov.b64 {%0, %1}, %2;" : "=f"(x), "=f"(y) : "l"(d));
}

// ---------------- K1: weight-norm scales for v_node ----------------
__global__ void k_scales(const float* __restrict__ v_node, const float* __restrict__ g_node) {
    int w = (blockIdx.x * blockDim.x + threadIdx.x) >> 5;
    int lane = threadIdx.x & 31;
    const float* src = v_node + w * 512;
    float s = 0.f;
#pragma unroll
    for (int k = lane; k < 512; k += 32) { float v = src[k]; s += v * v; }
    s = warp_sum(s);
    if (lane == 0) d_scale_n[w] = g_node[w] * rsqrtf(s);
}

// ---------------- K_cond: one warp per channel c; cond staged in smem --------
__global__ void __launch_bounds__(128) k_cond(const float* __restrict__ cond,
                                              const float* __restrict__ vc,
                                              const float* __restrict__ gc,
                                              const float* __restrict__ bc) {
    __shared__ float cs[16 * 512];   // 32 KB
    int tid = threadIdx.x;
    for (int i = tid; i < 16 * 512 / 4; i += 128)
        ((float4*)cs)[i] = ((const float4*)cond)[i];
    __syncthreads();

    int c = blockIdx.x * 4 + (tid >> 5);
    int lane = tid & 31;
    const float* vr = vc + (size_t)c * 512;

    float v[16];
    float q = 0.f;
#pragma unroll
    for (int i = 0; i < 16; i++) { v[i] = vr[lane + 32 * i]; q = fmaf(v[i], v[i], q); }
    q = warp_sum(q);
    float sc = gc[c] * rsqrtf(q);
    float bias = bc[c];

#pragma unroll
    for (int b = 0; b < 16; b++) {
        const float* cr = cs + b * 512;
        float s = 0.f;
#pragma unroll
        for (int i = 0; i < 16; i++) s = fmaf(cr[lane + 32 * i], v[i], s);
        s = warp_sum(s);
        if (lane == 0) {
            float r = fmaf(s, sc, bias);
            if (c < 128) d_gamma[b * 128 + c] = r + 1.f;
            else         d_beta[b * 128 + (c - 128)] = r;
        }
    }
}

// ---------------- Fused GEMM: nodes tile -> AB tile (+ bf fold + row sums) ----
// grid 128 x 128 threads. BM=32 rows per block. Inner loops use fma.rn.f32x2
// with M-dimension pairing: A-operand pairs come free from smem (consecutive m),
// only B needs replication packs (ALU pipe, parallel to FMA pipe).
__global__ void __launch_bounds__(128) k_fused(const float* __restrict__ nf,
                                               const float* __restrict__ vn,
                                               const float* __restrict__ bn,
                                               const float* __restrict__ wf,
                                               const float* __restrict__ bf) {
    __shared__ float As1[16][32];    // [k][m]  (rows 128B, 16B-aligned pair loads)
    __shared__ float Bs1[16][128];   // [k][n]
    __shared__ float Ns[128][34];    // [k2][m] transposed nodes tile; pad 34 keeps
                                     // (34*k + even m)*4 8B-aligned for ull loads
    __shared__ float Bs2[16][256];   // [k][n]

    int tid = threadIdx.x;
    int mb = blockIdx.x * 32;
    int m0 = (tid >> 5) * 8;         // warp-uniform
    int n0 = (tid & 31) * 4;         // phase-1 col group

    // -------- Phase 1: N1(32x128) = relu(nf @ (vn*scale)^T + bn) --------
    int ar = tid & 31, ac = (tid >> 5) * 4;
    int br = tid >> 2, bk = (tid & 3) * 4;

    const float* Arow = nf + (size_t)(mb + ar) * 512 + ac;
    const float* B0 = vn + (size_t)(br +  0) * 512 + bk;
    const float* B1 = vn + (size_t)(br + 32) * 512 + bk;
    const float* B2 = vn + (size_t)(br + 64) * 512 + bk;
    const float* B3 = vn + (size_t)(br + 96) * 512 + bk;

    float4 aR = *(const float4*)Arow;
    float4 bR0 = *(const float4*)B0, bR1 = *(const float4*)B1;
    float4 bR2 = *(const float4*)B2, bR3 = *(const float4*)B3;

    // accp[p][j]: rows (m0+2p, m0+2p+1), col n0+j
    ull accp[4][4];
#pragma unroll
    for (int p = 0; p < 4; p++)
#pragma unroll
        for (int j = 0; j < 4; j++) accp[p][j] = 0ull;

#pragma unroll 1
    for (int c = 0; c < 32; c++) {
        __syncthreads();
        As1[ac + 0][ar] = aR.x; As1[ac + 1][ar] = aR.y;
        As1[ac + 2][ar] = aR.z; As1[ac + 3][ar] = aR.w;
        Bs1[bk + 0][br +  0] = bR0.x; Bs1[bk + 1][br +  0] = bR0.y; Bs1[bk + 2][br +  0] = bR0.z; Bs1[bk + 3][br +  0] = bR0.w;
        Bs1[bk + 0][br + 32] = bR1.x; Bs1[bk + 1][br + 32] = bR1.y; Bs1[bk + 2][br + 32] = bR1.z; Bs1[bk + 3][br + 32] = bR1.w;
        Bs1[bk + 0][br + 64] = bR2.x; Bs1[bk + 1][br + 64] = bR2.y; Bs1[bk + 2][br + 64] = bR2.z; Bs1[bk + 3][br + 64] = bR2.w;
        Bs1[bk + 0][br + 96] = bR3.x; Bs1[bk + 1][br + 96] = bR3.y; Bs1[bk + 2][br + 96] = bR3.z; Bs1[bk + 3][br + 96] = bR3.w;
        __syncthreads();
        if (c < 31) {
            int k0 = (c + 1) * 16;
            aR  = *(const float4*)(Arow + k0);
            bR0 = *(const float4*)(B0 + k0);
            bR1 = *(const float4*)(B1 + k0);
            bR2 = *(const float4*)(B2 + k0);
            bR3 = *(const float4*)(B3 + k0);
        }
#pragma unroll
        for (int k = 0; k < 16; k++) {
            ulonglong2 apLo = *(const ulonglong2*)&As1[k][m0];      // (a0,a1),(a2,a3)
            ulonglong2 apHi = *(const ulonglong2*)&As1[k][m0 + 4];  // (a4,a5),(a6,a7)
            float4 b = *(const float4*)&Bs1[k][n0];
            ull bx = pack2(b.x, b.x), by = pack2(b.y, b.y);
            ull bz = pack2(b.z, b.z), bw = pack2(b.w, b.w);
            ull ap[4] = {apLo.x, apLo.y, apHi.x, apHi.y};
#pragma unroll
            for (int p = 0; p < 4; p++) {
                accp[p][0] = fma2(ap[p], bx, accp[p][0]);
                accp[p][1] = fma2(ap[p], by, accp[p][1]);
                accp[p][2] = fma2(ap[p], bz, accp[p][2]);
                accp[p][3] = fma2(ap[p], bw, accp[p][3]);
            }
        }
    }

    // epilogue: relu(acc*scale+bias) -> Ns[n][m]
    {
        float4 sc4 = *(const float4*)&d_scale_n[n0];
        float4 bb4 = *(const float4*)&bn[n0];
        float scj[4] = {sc4.x, sc4.y, sc4.z, sc4.w};
        float bbj[4] = {bb4.x, bb4.y, bb4.z, bb4.w};
        __syncthreads();
#pragma unroll
        for (int p = 0; p < 4; p++) {
#pragma unroll
            for (int j = 0; j < 4; j++) {
                float lo, hi;
                unpack2(lo, hi, accp[p][j]);
                Ns[n0 + j][m0 + 2 * p + 0] = fmaxf(fmaf(lo, scj[j], bbj[j]), 0.f);
                Ns[n0 + j][m0 + 2 * p + 1] = fmaxf(fmaf(hi, scj[j], bbj[j]), 0.f);
            }
        }
    }
    __syncthreads();

    // -------- Phase 2: AB(32x256) = Ns^T @ Wt^T, K=128 --------
    int lane = tid & 31;
    int n2 = lane * 8;                       // output col group (8 cols)
    int br2 = tid >> 2, bk2 = (tid & 3) * 4; // B loader
    int roff[8];
#pragma unroll
    for (int j = 0; j < 8; j++) {
        int n = br2 + 32 * j;
        roff[j] = (j < 4) ? n * 256 + bk2 : (n - 128) * 256 + 128 + bk2;
    }

    float4 w0 = *(const float4*)(wf + roff[0]);
    float4 w1 = *(const float4*)(wf + roff[1]);
    float4 w2 = *(const float4*)(wf + roff[2]);
    float4 w3 = *(const float4*)(wf + roff[3]);
    float4 w4 = *(const float4*)(wf + roff[4]);
    float4 w5 = *(const float4*)(wf + roff[5]);
    float4 w6 = *(const float4*)(wf + roff[6]);
    float4 w7 = *(const float4*)(wf + roff[7]);

    // accp2[p][j]: rows (m0+2p, m0+2p+1), col n2+j
    ull accp2[4][8];
#pragma unroll
    for (int p = 0; p < 4; p++)
#pragma unroll
        for (int j = 0; j < 8; j++) accp2[p][j] = 0ull;

#pragma unroll 1
    for (int c = 0; c < 8; c++) {
        __syncthreads();
        Bs2[bk2 + 0][br2 +   0] = w0.x; Bs2[bk2 + 1][br2 +   0] = w0.y; Bs2[bk2 + 2][br2 +   0] = w0.z; Bs2[bk2 + 3][br2 +   0] = w0.w;
        Bs2[bk2 + 0][br2 +  32] = w1.x; Bs2[bk2 + 1][br2 +  32] = w1.y; Bs2[bk2 + 2][br2 +  32] = w1.z; Bs2[bk2 + 3][br2 +  32] = w1.w;
        Bs2[bk2 + 0][br2 +  64] = w2.x; Bs2[bk2 + 1][br2 +  64] = w2.y; Bs2[bk2 + 2][br2 +  64] = w2.z; Bs2[bk2 + 3][br2 +  64] = w2.w;
        Bs2[bk2 + 0][br2 +  96] = w3.x; Bs2[bk2 + 1][br2 +  96] = w3.y; Bs2[bk2 + 2][br2 +  96] = w3.z; Bs2[bk2 + 3][br2 +  96] = w3.w;
        Bs2[bk2 + 0][br2 + 128] = w4.x; Bs2[bk2 + 1][br2 + 128] = w4.y; Bs2[bk2 + 2][br2 + 128] = w4.z; Bs2[bk2 + 3][br2 + 128] = w4.w;
        Bs2[bk2 + 0][br2 + 160] = w5.x; Bs2[bk2 + 1][br2 + 160] = w5.y; Bs2[bk2 + 2][br2 + 160] = w5.z; Bs2[bk2 + 3][br2 + 160] = w5.w;
        Bs2[bk2 + 0][br2 + 192] = w6.x; Bs2[bk2 + 1][br2 + 192] = w6.y; Bs2[bk2 + 2][br2 + 192] = w6.z; Bs2[bk2 + 3][br2 + 192] = w6.w;
        Bs2[bk2 + 0][br2 + 224] = w7.x; Bs2[bk2 + 1][br2 + 224] = w7.y; Bs2[bk2 + 2][br2 + 224] = w7.z; Bs2[bk2 + 3][br2 + 224] = w7.w;
        __syncthreads();
        if (c < 7) {
            int k0 = (c + 1) * 16;
            w0 = *(const float4*)(wf + roff[0] + k0);
            w1 = *(const float4*)(wf + roff[1] + k0);
            w2 = *(const float4*)(wf + roff[2] + k0);
            w3 = *(const float4*)(wf + roff[3] + k0);
            w4 = *(const float4*)(wf + roff[4] + k0);
            w5 = *(const float4*)(wf + roff[5] + k0);
            w6 = *(const float4*)(wf + roff[6] + k0);
            w7 = *(const float4*)(wf + roff[7] + k0);
        }
        int kbase = c * 16;
#pragma unroll
        for (int k = 0; k < 16; k++) {
            const float* nrow = &Ns[kbase + k][0];
            // 8B-aligned broadcast pair loads (pad 34 => (34k + even)*4 % 8 == 0)
            ull ap[4];
            ap[0] = *(const ull*)&nrow[m0 + 0];
            ap[1] = *(const ull*)&nrow[m0 + 2];
            ap[2] = *(const ull*)&nrow[m0 + 4];
            ap[3] = *(const ull*)&nrow[m0 + 6];
            float4 bLo = *(const float4*)&Bs2[k][n2];
            float4 bHi = *(const float4*)&Bs2[k][n2 + 4];
            ull bp[8];
            bp[0] = pack2(bLo.x, bLo.x); bp[1] = pack2(bLo.y, bLo.y);
            bp[2] = pack2(bLo.z, bLo.z); bp[3] = pack2(bLo.w, bLo.w);
            bp[4] = pack2(bHi.x, bHi.x); bp[5] = pack2(bHi.y, bHi.y);
            bp[6] = pack2(bHi.z, bHi.z); bp[7] = pack2(bHi.w, bHi.w);
#pragma unroll
            for (int p = 0; p < 4; p++)
#pragma unroll
                for (int j = 0; j < 8; j++)
                    accp2[p][j] = fma2(ap[p], bp[j], accp2[p][j]);
        }
    }

    // -------- Epilogue: fold b_film into A half, write AB, emit row sums --------
    // lanes 0..15 hold cols [0,128) (A half); lanes 16..31 hold cols [128,256) (B half)
    float fj[8] = {0.f, 0.f, 0.f, 0.f, 0.f, 0.f, 0.f, 0.f};
    if (lane < 16) {
        float4 f0 = *(const float4*)(bf + n2);
        float4 f1 = *(const float4*)(bf + n2 + 4);
        fj[0] = f0.x; fj[1] = f0.y; fj[2] = f0.z; fj[3] = f0.w;
        fj[4] = f1.x; fj[5] = f1.y; fj[6] = f1.z; fj[7] = f1.w;
    }

#pragma unroll
    for (int p = 0; p < 4; p++) {
        float lo[8], hi[8];
#pragma unroll
        for (int j = 0; j < 8; j++) {
            unpack2(lo[j], hi[j], accp2[p][j]);
            lo[j] += fj[j];
            hi[j] += fj[j];
        }
        int r0 = m0 + 2 * p, r1 = r0 + 1;
        float* dst0 = &d_AB[(size_t)(mb + r0) * 256 + n2];
        float* dst1 = &d_AB[(size_t)(mb + r1) * 256 + n2];
        *(float4*)(dst0 + 0) = make_float4(lo[0], lo[1], lo[2], lo[3]);
        *(float4*)(dst0 + 4) = make_float4(lo[4], lo[5], lo[6], lo[7]);
        *(float4*)(dst1 + 0) = make_float4(hi[0], hi[1], hi[2], hi[3]);
        *(float4*)(dst1 + 4) = make_float4(hi[4], hi[5], hi[6], hi[7]);

        // row sums within each 16-lane half (xor <= 8 keeps halves separate)
        float s0 = ((lo[0] + lo[1]) + (lo[2] + lo[3])) + ((lo[4] + lo[5]) + (lo[6] + lo[7]));
        float s1 = ((hi[0] + hi[1]) + (hi[2] + hi[3])) + ((hi[4] + hi[5]) + (hi[6] + hi[7]));
#pragma unroll
        for (int o = 8; o; o >>= 1) {
            s0 += __shfl_xor_sync(0xffffffffu, s0, o);
            s1 += __shfl_xor_sync(0xffffffffu, s1, o);
        }
        if (lane == 0)  { d_sumA[mb + r0] = s0; d_sumA[mb + r1] = s1; }
        if (lane == 16) { d_sumB[mb + r0] = s0; d_sumB[mb + r1] = s1; }
    }
}

// ---------------- K4: per-edge gather + layernorm + FiLM + relu ----------------
// Full warp per edge (contiguous 512B accesses = 4 wavefronts/instr). Each lane
// precomputes one edge's (idx, mean) in the prologue (k_mean kernel deleted:
// it was launch/tail-bound at ~6us regardless of occupancy); the loop shuffles
// idx+mean from lane e (2 SHFL replaces 1 broadcast LDG + whole extra kernel).
// Variance: 5-level SHFL butterfly (redux.f32 does not exist on sm_103).
// A-row cached in registers keyed on v1 (sorted edges, run-length ~64).
// dtype probe: int64 (LE) buffer has zero odd words; int32 has nonzero tail words.
__global__ void __launch_bounds__(256) k_film(const int* __restrict__ e32,
                                              float* __restrict__ out) {
    int gw = (blockIdx.x * 256 + threadIdx.x) >> 5;
    int lane = threadIdx.x & 31;
    long long base = (long long)gw * 32;

    int stride = (e32[262143] == 0 && e32[262141] == 0) ? 2 : 1;
    int myi = e32[(size_t)(base + lane) * stride];
    int mv1 = myi >> 8;
    int mv2 = ((myi >> 16) << 8) | (myi & 255);
    float m_my = (d_sumA[mv1] + d_sumB[mv2]) * 0.0078125f;   // /128

    int gb = (int)(base >> 14);          // batch slot (32 | 16384)
    float4 gv = *(const float4*)(d_gamma + gb * 128 + lane * 4);
    float4 bv = *(const float4*)(d_beta  + gb * 128 + lane * 4);

    int prev = -1;
    float4 xa = make_float4(0.f, 0.f, 0.f, 0.f);

#pragma unroll 4
    for (int e = 0; e < 32; e++) {
        int idx = __shfl_sync(0xffffffffu, myi, e);
        float mean = __shfl_sync(0xffffffffu, m_my, e);
        int v1 = idx >> 8;
        int v2 = ((idx >> 16) << 8) | (idx & 255);

        if (v1 != prev) {                               // warp-uniform branch
            xa = *(const float4*)(d_AB + (size_t)v1 * 256 + lane * 4);
            prev = v1;
        }
        float4 xb = *(const float4*)(d_AB + (size_t)v2 * 256 + 128 + lane * 4);
        float4 x;
        x.x = xa.x + xb.x;
        x.y = xa.y + xb.y;
        x.z = xa.z + xb.z;
        x.w = xa.w + xb.w;

        float s2 = x.x * x.x;
        s2 = fmaf(x.y, x.y, s2);
        s2 = fmaf(x.z, x.z, s2);
        s2 = fmaf(x.w, x.w, s2);
#pragma unroll
        for (int o = 16; o; o >>= 1) s2 += __shfl_xor_sync(0xffffffffu, s2, o);

        float var = fmaf(s2, 0.0078125f, -mean * mean);
        float rs = rsqrtf(var + 1e-5f);

        float4 y;
        y.x = fmaxf(fmaf((x.x - mean) * rs, gv.x, bv.x), 0.f);
        y.y = fmaxf(fmaf((x.y - mean) * rs, gv.y, bv.y), 0.f);
        y.z = fmaxf(fmaf((x.z - mean) * rs, gv.z, bv.z), 0.f);
        y.w = fmaxf(fmaf((x.w - mean) * rs, gv.w, bv.w), 0.f);
        __stcs((float4*)(out + (size_t)(base + e) * 128 + lane * 4), y);
    }
}

// ---------------- launch ----------------
extern "C" void kernel_launch(void* const* d_in, const int* in_sizes, int n_in,
                              void* d_out, int out_size) {
    const float* node_feats   = (const float*)d_in[0];
    const float* cond_feats   = (const float*)d_in[1];
    const int* eidx32         = (const int*)d_in[2];
    const float* v_node       = (const float*)d_in[3];
    const float* g_node       = (const float*)d_in[4];
    const float* b_node       = (const float*)d_in[5];
    const float* v_cond       = (const float*)d_in[6];
    const float* g_cond       = (const float*)d_in[7];
    const float* b_cond       = (const float*)d_in[8];
    const float* w_film       = (const float*)d_in[9];
    const float* b_film       = (const float*)d_in[10];
    float* out = (float*)d_out;

    k_scales<<<16, 256>>>(v_node, g_node);                              // 128 warps
    k_cond<<<64, 128>>>(cond_feats, v_cond, g_cond, b_cond);            // 256 warps
    k_fused<<<128, 128>>>(node_feats, v_node, b_node, w_film, b_film);  // both GEMMs (f32x2)
    k_film<<<1024, 256>>>(eidx32, out);                                 // 262144 edges
}